// round 9
// baseline (speedup 1.0000x reference)
#include <cuda_runtime.h>

#define Q_  32
#define LQ_ 32
#define D_  256
#define LD_ 192
#define H_  768
#define DT_ 128
#define DC_ 768

// Scratch (allocation-free: __device__ globals)
__device__ float g_doc_reps[(size_t)D_ * LD_ * DT_];   // 25.2 MB
__device__ float g_qry_reps[(size_t)Q_ * LQ_ * DT_];
__device__ float g_doc_cls[(size_t)D_ * DC_];
__device__ float g_qry_cls[(size_t)Q_ * DC_];
__device__ float g_scores[(size_t)Q_ * D_];
__device__ float g_loss[1];

// ---------------------------------------------------------------------------
// Generic SGEMM: C[m,n] (+)= act( sum_k A[m*lda+k] * B(k,n) + bias[n] )
// TRANSB=false: B[k*ldb+n]; TRANSB=true: B[n*ldb+k]
// BM=BN=128, BK=8, 256 threads, 8x8 microtile. K%8==0, N%4==0 for all uses.
// ---------------------------------------------------------------------------
template <bool TRANSB>
__global__ __launch_bounds__(256) void sgemm(
    const float* __restrict__ A, int lda,
    const float* __restrict__ B, int ldb,
    const float* __restrict__ bias,
    float* __restrict__ C, int ldc,
    int M, int N, int K, int relu, int accum)
{
    const int BM = 128, BN = 128, BK = 8;
    __shared__ float As[BK][BM];
    __shared__ float Bs[BK][BN];

    int tid = threadIdx.x;
    int bm = blockIdx.x * BM;
    int bn = blockIdx.y * BN;
    int tx = tid % 16;
    int ty = tid / 16;

    float acc[8][8];
#pragma unroll
    for (int i = 0; i < 8; i++)
#pragma unroll
        for (int j = 0; j < 8; j++) acc[i][j] = 0.f;

    int a_row = tid / 2;            // 0..127
    int a_col = (tid % 2) * 4;      // 0 or 4
    int b_row = tid / 32;           // 0..7
    int b_col = (tid % 32) * 4;     // 0..124
    int bt_n = tid / 2;             // 0..127
    int bt_k = (tid % 2) * 4;       // 0 or 4

    for (int k0 = 0; k0 < K; k0 += BK) {
        float4 av = make_float4(0.f, 0.f, 0.f, 0.f);
        if (bm + a_row < M)
            av = *reinterpret_cast<const float4*>(A + (size_t)(bm + a_row) * lda + k0 + a_col);
        As[a_col + 0][a_row] = av.x;
        As[a_col + 1][a_row] = av.y;
        As[a_col + 2][a_row] = av.z;
        As[a_col + 3][a_row] = av.w;

        if (!TRANSB) {
            float4 bv = make_float4(0.f, 0.f, 0.f, 0.f);
            if (bn + b_col < N)
                bv = *reinterpret_cast<const float4*>(B + (size_t)(k0 + b_row) * ldb + bn + b_col);
            *reinterpret_cast<float4*>(&Bs[b_row][b_col]) = bv;
        } else {
            float4 bv = make_float4(0.f, 0.f, 0.f, 0.f);
            if (bn + bt_n < N)
                bv = *reinterpret_cast<const float4*>(B + (size_t)(bn + bt_n) * ldb + k0 + bt_k);
            Bs[bt_k + 0][bt_n] = bv.x;
            Bs[bt_k + 1][bt_n] = bv.y;
            Bs[bt_k + 2][bt_n] = bv.z;
            Bs[bt_k + 3][bt_n] = bv.w;
        }
        __syncthreads();

#pragma unroll
        for (int kk = 0; kk < BK; kk++) {
            float a[8], b[8];
#pragma unroll
            for (int i = 0; i < 8; i++) a[i] = As[kk][ty * 8 + i];
#pragma unroll
            for (int j = 0; j < 8; j++) b[j] = Bs[kk][tx * 8 + j];
#pragma unroll
            for (int i = 0; i < 8; i++)
#pragma unroll
                for (int j = 0; j < 8; j++)
                    acc[i][j] += a[i] * b[j];
        }
        __syncthreads();
    }

#pragma unroll
    for (int i = 0; i < 8; i++) {
        int m = bm + ty * 8 + i;
        if (m >= M) continue;
#pragma unroll
        for (int j = 0; j < 8; j++) {
            int n = bn + tx * 8 + j;
            if (n >= N) continue;
            float v = acc[i][j];
            if (bias) v += bias[n];
            if (relu) v = fmaxf(v, 0.f);
            if (accum) v += C[(size_t)m * ldc + n];
            C[(size_t)m * ldc + n] = v;
        }
    }
}

// Disambiguate the two 1024-element inputs on device: the attention mask is
// all exactly 1.0f (bits 0x3F800000); input ids are int32 < 1000.
__device__ __forceinline__ bool is_mask_arr(const void* p) {
    const unsigned* u = (const unsigned*)p;
    return u[0] == 0x3F800000u && u[1] == 0x3F800000u && u[2] == 0x3F800000u;
}

// ---------------------------------------------------------------------------
// Sparse exact-match token scoring. Block = (q, chunk of 8 docs).
// g_scores[q,d] = sum_{i=1..LQ-1} qmask[q,i] *
//                 max_{j: doc_ids[d,j]==qry_ids[q,i]} dot(qrep[q,i], drep[d,j])
// (max clamped at 0 == reference's mask-then-max since relu dots are >= 0)
// ---------------------------------------------------------------------------
__global__ __launch_bounds__(128) void tok_kernel(
    const void* __restrict__ cand_a, const void* __restrict__ cand_b,
    const int* __restrict__ dids_g,
    float* __restrict__ scores)
{
    bool a_mask = is_mask_arr(cand_a);
    const int*   qids_g  = (const int*)  (a_mask ? cand_b : cand_a);
    const float* qmask_g = (const float*)(a_mask ? cand_a : cand_b);

    __shared__ float qs[LQ_][DT_];     // 16 KB
    __shared__ int   s_qids[LQ_];
    __shared__ float s_qmask[LQ_];
    __shared__ int   s_dids[LD_];
    __shared__ float warp_acc[4];

    int q   = blockIdx.x;
    int d0  = blockIdx.y * 8;
    int tid = threadIdx.x;
    int lane = tid & 31;
    int w    = tid >> 5;

    for (int t = tid; t < LQ_ * DT_; t += 128)
        qs[t / DT_][t % DT_] = g_qry_reps[(size_t)q * LQ_ * DT_ + t];
    if (tid < LQ_) {
        s_qids[tid]  = qids_g[q * LQ_ + tid];
        s_qmask[tid] = qmask_g[q * LQ_ + tid];
    }
    __syncthreads();

    for (int dd = 0; dd < 8; dd++) {
        int d = d0 + dd;
        for (int t = tid; t < LD_; t += 128)
            s_dids[t] = dids_g[d * LD_ + t];
        __syncthreads();

        const float* drep = g_doc_reps + (size_t)d * LD_ * DT_;
        float acc = 0.f;

        for (int i = 1 + w; i < LQ_; i += 4) {
            int tok = s_qids[i];
            float best = 0.f;
#pragma unroll
            for (int jb = 0; jb < LD_; jb += 32) {
                int j = jb + lane;
                unsigned mask = __ballot_sync(0xffffffffu, s_dids[j] == tok);
                while (mask) {
                    int jj = jb + (__ffs(mask) - 1);
                    mask &= mask - 1;
                    const float* dr = drep + (size_t)jj * DT_;
                    float p = qs[i][lane]      * dr[lane]
                            + qs[i][lane + 32] * dr[lane + 32]
                            + qs[i][lane + 64] * dr[lane + 64]
                            + qs[i][lane + 96] * dr[lane + 96];
#pragma unroll
                    for (int off = 16; off > 0; off >>= 1)
                        p += __shfl_xor_sync(0xffffffffu, p, off);
                    best = fmaxf(best, p);
                }
            }
            acc += best * s_qmask[i];
        }

        if (lane == 0) warp_acc[w] = acc;
        __syncthreads();
        if (tid == 0)
            scores[q * D_ + d] = warp_acc[0] + warp_acc[1] + warp_acc[2] + warp_acc[3];
        __syncthreads();
    }
}

// ---------------------------------------------------------------------------
// Cross-entropy loss -> g_loss[0]. One block, one warp per query row (D=256).
// ---------------------------------------------------------------------------
__global__ __launch_bounds__(1024) void loss_kernel(
    const float* __restrict__ scores, const int* __restrict__ gs)
{
    __shared__ float wloss[32];
    int tid = threadIdx.x;
    int lane = tid & 31;
    int w = tid >> 5;

    const float* row = scores + (size_t)w * D_;
    float m = -1e30f;
    for (int c = lane; c < D_; c += 32) m = fmaxf(m, row[c]);
#pragma unroll
    for (int off = 16; off > 0; off >>= 1)
        m = fmaxf(m, __shfl_xor_sync(0xffffffffu, m, off));
    float s = 0.f;
    for (int c = lane; c < D_; c += 32) s += expf(row[c] - m);
#pragma unroll
    for (int off = 16; off > 0; off >>= 1)
        s += __shfl_xor_sync(0xffffffffu, s, off);

    int group = 8;
    if (gs) {
        int gv = gs[0];                    // low word OK for i32 and LE i64
        if (gv >= 1 && gv * 31 < D_) group = gv;
    }
    int label = w * group;
    float logp = row[label] - m - logf(s);
    if (lane == 0) wloss[w] = -logp;
    __syncthreads();
    if (tid == 0) {
        float t = 0.f;
        for (int i = 0; i < 32; i++) t += wloss[i];
        g_loss[0] = t / 32.f;
    }
}

// ---------------------------------------------------------------------------
// Output layout by out_size: [loss] | [scores] | [loss, scores, 0-tail]
// ---------------------------------------------------------------------------
__global__ void layout_kernel(float* __restrict__ out, int out_size, int mode)
{
    int i = blockIdx.x * blockDim.x + threadIdx.x;
    if (i >= out_size) return;
    if (mode == 0) {
        if (i == 0) out[0] = g_loss[0];
    } else if (mode == 1) {
        out[i] = (i < Q_ * D_) ? g_scores[i] : 0.f;
    } else {
        if (i == 0) out[0] = g_loss[0];
        else out[i] = (i - 1 < Q_ * D_) ? g_scores[i - 1] : 0.f;
    }
}

// Diagnostic sentinel (mapping failure -> decodable signal, not a crash)
__global__ void diag_kernel(float* out, int missing_mask, int n)
{
    int i = blockIdx.x * blockDim.x + threadIdx.x;
    if (i < n) out[i] = (i == 0) ? (-1.0e6f - (float)missing_mask) : 0.f;
}

// ---------------------------------------------------------------------------
extern "C" void kernel_launch(void* const* d_in, const int* in_sizes, int n_in,
                              void* d_out, int out_size)
{
    const float* qry_hidden = nullptr;   // 786432 elems
    const float* doc_hidden = nullptr;   // 37748736
    const void*  doc_ids    = nullptr;   // 49152
    const float* tok_w      = nullptr;   // 98304
    const float* tok_b      = nullptr;   // 128
    const float* cls_w      = nullptr;   // 589824
    const float* cls_b      = nullptr;   // 768
    const int*   gsize      = nullptr;   // 1
    const void*  cand_a     = nullptr;   // 1024 (ids or mask)
    const void*  cand_b     = nullptr;   // 1024

    // Convention guard: elements (per stub) with byte fallback.
    long long div = 0;
    for (int i = 0; i < n_in; i++) {
        if (in_sizes[i] == 37748736)  { div = 1; break; }   // doc_hidden elems
        if (in_sizes[i] == 150994944) { div = 4; break; }   // doc_hidden bytes
    }
    if (div == 0) div = 1;

    for (int i = 0; i < n_in; i++) {
        long long sz = (long long)in_sizes[i] / div;
        switch (sz) {
            case 786432:   qry_hidden = (const float*)d_in[i]; break;
            case 37748736: doc_hidden = (const float*)d_in[i]; break;
            case 49152:    doc_ids    = d_in[i];               break;
            case 98304:    tok_w      = (const float*)d_in[i]; break;
            case 128:      tok_b      = (const float*)d_in[i]; break;
            case 589824:   cls_w      = (const float*)d_in[i]; break;
            case 768:      cls_b      = (const float*)d_in[i]; break;
            case 1:        gsize      = (const int*)d_in[i];   break;
            case 1024:
                if (!cand_a) cand_a = d_in[i]; else cand_b = d_in[i];
                break;
            default:
                if (sz == 2 && div == 4) gsize = (const int*)d_in[i]; // i64 scalar
                break;
        }
    }

    float* out = (float*)d_out;

    int missing = 0;
    if (!qry_hidden) missing |= 1;
    if (!doc_hidden) missing |= 2;
    if (!doc_ids)    missing |= 4;
    if (!tok_w)      missing |= 8;
    if (!tok_b)      missing |= 16;
    if (!cls_w)      missing |= 32;
    if (!cls_b)      missing |= 64;
    if (!cand_a)     missing |= 128;
    if (!cand_b)     missing |= 256;
    if (missing) {
        int n = out_size > 0 ? out_size : 1;
        diag_kernel<<<(n + 255) / 256, 256>>>(out, missing, n);
        return;
    }

    float *doc_reps, *qry_reps, *doc_cls, *qry_cls, *scores;
    cudaGetSymbolAddress((void**)&doc_reps, g_doc_reps);
    cudaGetSymbolAddress((void**)&qry_reps, g_qry_reps);
    cudaGetSymbolAddress((void**)&doc_cls,  g_doc_cls);
    cudaGetSymbolAddress((void**)&qry_cls,  g_qry_cls);
    cudaGetSymbolAddress((void**)&scores,   g_scores);

    // 1) doc_reps = relu(doc_hidden @ tok_w + tok_b)   M=49152, N=128, K=768
    {
        dim3 grid((D_ * LD_ + 127) / 128, 1);
        sgemm<false><<<grid, 256>>>(doc_hidden, H_, tok_w, DT_, tok_b,
                                    doc_reps, DT_, D_ * LD_, DT_, H_, 1, 0);
    }
    // 2) qry_reps = relu(qry_hidden @ tok_w + tok_b)   M=1024
    {
        dim3 grid((Q_ * LQ_ + 127) / 128, 1);
        sgemm<false><<<grid, 256>>>(qry_hidden, H_, tok_w, DT_, tok_b,
                                    qry_reps, DT_, Q_ * LQ_, DT_, H_, 1, 0);
    }
    // 3) doc_cls = doc_hidden[:,0,:] @ cls_w + cls_b   (lda = LD_*H_)
    {
        dim3 grid((D_ + 127) / 128, (DC_ + 127) / 128);
        sgemm<false><<<grid, 256>>>(doc_hidden, LD_ * H_, cls_w, DC_, cls_b,
                                    doc_cls, DC_, D_, DC_, H_, 0, 0);
    }
    // 4) qry_cls = qry_hidden[:,0,:] @ cls_w + cls_b   (lda = LQ_*H_)
    {
        dim3 grid(1, (DC_ + 127) / 128);
        sgemm<false><<<grid, 256>>>(qry_hidden, LQ_ * H_, cls_w, DC_, cls_b,
                                    qry_cls, DC_, Q_, DC_, H_, 0, 0);
    }
    // 5) sparse exact-match token scores -> g_scores
    {
        dim3 grid(Q_, D_ / 8);
        tok_kernel<<<grid, 128>>>(cand_a, cand_b, (const int*)doc_ids, scores);
    }
    // 6) g_scores += qry_cls @ doc_cls^T   (M=32, N=256, K=768, accumulate)
    {
        dim3 grid(1, (D_ + 127) / 128);
        sgemm<true><<<grid, 256>>>(qry_cls, DC_, doc_cls, DC_, (const float*)nullptr,
                                   scores, D_, Q_, D_, DC_, 0, 1);
    }
    // 7) loss -> g_loss
    loss_kernel<<<1, 1024>>>(scores, gsize);
    // 8) lay out per out_size (expected 1 + 32*256 = 8193)
    int mode = (out_size == 1) ? 0 : (out_size == Q_ * D_) ? 1 : 2;
    layout_kernel<<<(out_size + 255) / 256, 256>>>(out, out_size, mode);
}

// round 10
// speedup vs baseline: 2.5212x; 2.5212x over previous
#include <cuda_runtime.h>

#define Q_  32
#define LQ_ 32
#define D_  256
#define LD_ 192
#define H_  768
#define DT_ 128
#define DC_ 768

// Scratch (allocation-free: __device__ globals)
__device__ float g_doc_reps[(size_t)D_ * LD_ * DT_];   // 25.2 MB
__device__ float g_qry_reps[(size_t)Q_ * LQ_ * DT_];
__device__ float g_doc_cls[(size_t)D_ * DC_];
__device__ float g_qry_cls[(size_t)Q_ * DC_];
__device__ float g_scores[(size_t)Q_ * D_];
__device__ float g_loss[1];

// Mega-GEMM block ranges
#define NB_DOCREP 384                      // 49152/128 m-tiles, N=128
#define NB_QRYREP 8                        // 1024/128 m-tiles
#define NB_DOCCLS 12                       // 2 m-tiles x 6 n-tiles
#define NB_QRYCLS 6                        // 1 m-tile  x 6 n-tiles
#define NB_TOTAL  (NB_DOCREP + NB_QRYREP + NB_DOCCLS + NB_QRYCLS)

// ---------------------------------------------------------------------------
// Fused mega-GEMM: one launch covers all four projections (independent,
// same K=768, same 128x128x8 tile machinery). Per-block segment dispatch.
//   C[m,n] = act( sum_k A[m*lda+k] * B[k*ldb+n] + bias[n] )
// ---------------------------------------------------------------------------
__global__ __launch_bounds__(256) void mega_gemm(
    const float* __restrict__ doc_hidden,
    const float* __restrict__ qry_hidden,
    const float* __restrict__ tok_w, const float* __restrict__ tok_b,
    const float* __restrict__ cls_w, const float* __restrict__ cls_b,
    float* __restrict__ doc_reps, float* __restrict__ qry_reps,
    float* __restrict__ doc_cls,  float* __restrict__ qry_cls)
{
    const int BK = 8;
    __shared__ float As[BK][128];
    __shared__ float Bs[BK][128];

    // --- segment dispatch ---
    const float* A; const float* B; const float* bias; float* C;
    int lda, ldb, ldc, M, bm, bn, relu;
    int b = blockIdx.x;
    if (b < NB_DOCREP) {
        A = doc_hidden; lda = H_;        B = tok_w; ldb = DT_; bias = tok_b;
        C = doc_reps;   ldc = DT_;       M = D_ * LD_;
        bm = b * 128;   bn = 0;          relu = 1;
    } else if (b < NB_DOCREP + NB_QRYREP) {
        int t = b - NB_DOCREP;
        A = qry_hidden; lda = H_;        B = tok_w; ldb = DT_; bias = tok_b;
        C = qry_reps;   ldc = DT_;       M = Q_ * LQ_;
        bm = t * 128;   bn = 0;          relu = 1;
    } else if (b < NB_DOCREP + NB_QRYREP + NB_DOCCLS) {
        int t = b - NB_DOCREP - NB_QRYREP;
        A = doc_hidden; lda = LD_ * H_;  B = cls_w; ldb = DC_; bias = cls_b;
        C = doc_cls;    ldc = DC_;       M = D_;
        bm = (t % 2) * 128; bn = (t / 2) * 128; relu = 0;
    } else {
        int t = b - NB_DOCREP - NB_QRYREP - NB_DOCCLS;
        A = qry_hidden; lda = LQ_ * H_;  B = cls_w; ldb = DC_; bias = cls_b;
        C = qry_cls;    ldc = DC_;       M = Q_;
        bm = 0;         bn = t * 128;    relu = 0;
    }

    int tid = threadIdx.x;
    int tx = tid % 16;
    int ty = tid / 16;

    float acc[8][8];
#pragma unroll
    for (int i = 0; i < 8; i++)
#pragma unroll
        for (int j = 0; j < 8; j++) acc[i][j] = 0.f;

    int a_row = tid / 2;            // 0..127
    int a_col = (tid % 2) * 4;      // 0 or 4
    int b_row = tid / 32;           // 0..7
    int b_col = (tid % 32) * 4;     // 0..124

    for (int k0 = 0; k0 < H_; k0 += BK) {
        float4 av = make_float4(0.f, 0.f, 0.f, 0.f);
        if (bm + a_row < M)
            av = *reinterpret_cast<const float4*>(A + (size_t)(bm + a_row) * lda + k0 + a_col);
        As[a_col + 0][a_row] = av.x;
        As[a_col + 1][a_row] = av.y;
        As[a_col + 2][a_row] = av.z;
        As[a_col + 3][a_row] = av.w;

        *reinterpret_cast<float4*>(&Bs[b_row][b_col]) =
            *reinterpret_cast<const float4*>(B + (size_t)(k0 + b_row) * ldb + bn + b_col);
        __syncthreads();

#pragma unroll
        for (int kk = 0; kk < BK; kk++) {
            float4 a0 = *reinterpret_cast<const float4*>(&As[kk][ty * 8]);
            float4 a1 = *reinterpret_cast<const float4*>(&As[kk][ty * 8 + 4]);
            float4 b0 = *reinterpret_cast<const float4*>(&Bs[kk][tx * 8]);
            float4 b1 = *reinterpret_cast<const float4*>(&Bs[kk][tx * 8 + 4]);
            float a[8] = {a0.x, a0.y, a0.z, a0.w, a1.x, a1.y, a1.z, a1.w};
            float bb[8] = {b0.x, b0.y, b0.z, b0.w, b1.x, b1.y, b1.z, b1.w};
#pragma unroll
            for (int i = 0; i < 8; i++)
#pragma unroll
                for (int j = 0; j < 8; j++)
                    acc[i][j] += a[i] * bb[j];
        }
        __syncthreads();
    }

#pragma unroll
    for (int i = 0; i < 8; i++) {
        int m = bm + ty * 8 + i;
        if (m >= M) continue;
#pragma unroll
        for (int j = 0; j < 8; j++) {
            int n = bn + tx * 8 + j;
            float v = acc[i][j] + bias[n];
            if (relu) v = fmaxf(v, 0.f);
            C[(size_t)m * ldc + n] = v;
        }
    }
}

// Disambiguate the two 1024-element inputs on device: the attention mask is
// all exactly 1.0f (bits 0x3F800000); input ids are int32 < 1000.
__device__ __forceinline__ bool is_mask_arr(const void* p) {
    const unsigned* u = (const unsigned*)p;
    return u[0] == 0x3F800000u && u[1] == 0x3F800000u && u[2] == 0x3F800000u;
}

// ---------------------------------------------------------------------------
// Sparse exact-match token scoring. Block = (q, chunk of 8 docs).
// g_scores[q,d] = sum_{i=1..LQ-1} qmask[q,i] *
//                 max_{j: doc_ids[d,j]==qry_ids[q,i]} dot(qrep[q,i], drep[d,j])
// ---------------------------------------------------------------------------
__global__ __launch_bounds__(128) void tok_kernel(
    const void* __restrict__ cand_a, const void* __restrict__ cand_b,
    const int* __restrict__ dids_g,
    float* __restrict__ scores)
{
    bool a_mask = is_mask_arr(cand_a);
    const int*   qids_g  = (const int*)  (a_mask ? cand_b : cand_a);
    const float* qmask_g = (const float*)(a_mask ? cand_a : cand_b);

    __shared__ float qs[LQ_][DT_];     // 16 KB
    __shared__ int   s_qids[LQ_];
    __shared__ float s_qmask[LQ_];
    __shared__ int   s_dids[LD_];
    __shared__ float warp_acc[4];

    int q   = blockIdx.x;
    int d0  = blockIdx.y * 8;
    int tid = threadIdx.x;
    int lane = tid & 31;
    int w    = tid >> 5;

    for (int t = tid; t < LQ_ * DT_; t += 128)
        qs[t / DT_][t % DT_] = g_qry_reps[(size_t)q * LQ_ * DT_ + t];
    if (tid < LQ_) {
        s_qids[tid]  = qids_g[q * LQ_ + tid];
        s_qmask[tid] = qmask_g[q * LQ_ + tid];
    }
    __syncthreads();

    for (int dd = 0; dd < 8; dd++) {
        int d = d0 + dd;
        for (int t = tid; t < LD_; t += 128)
            s_dids[t] = dids_g[d * LD_ + t];
        __syncthreads();

        const float* drep = g_doc_reps + (size_t)d * LD_ * DT_;
        float acc = 0.f;

        for (int i = 1 + w; i < LQ_; i += 4) {
            int tok = s_qids[i];
            float best = 0.f;
#pragma unroll
            for (int jb = 0; jb < LD_; jb += 32) {
                int j = jb + lane;
                unsigned mask = __ballot_sync(0xffffffffu, s_dids[j] == tok);
                while (mask) {
                    int jj = jb + (__ffs(mask) - 1);
                    mask &= mask - 1;
                    const float* dr = drep + (size_t)jj * DT_;
                    float p = qs[i][lane]      * dr[lane]
                            + qs[i][lane + 32] * dr[lane + 32]
                            + qs[i][lane + 64] * dr[lane + 64]
                            + qs[i][lane + 96] * dr[lane + 96];
#pragma unroll
                    for (int off = 16; off > 0; off >>= 1)
                        p += __shfl_xor_sync(0xffffffffu, p, off);
                    best = fmaxf(best, p);
                }
            }
            acc += best * s_qmask[i];
        }

        if (lane == 0) warp_acc[w] = acc;
        __syncthreads();
        if (tid == 0)
            scores[q * D_ + d] = warp_acc[0] + warp_acc[1] + warp_acc[2] + warp_acc[3];
        __syncthreads();
    }
}

// ---------------------------------------------------------------------------
// scores[q,d] += dot(qry_cls[q,:], doc_cls[d,:]).  Grid (Q, D/8), 8 warps per
// block, warp w handles doc d0+w; lane-strided K with shfl reduce. Coalesced.
// ---------------------------------------------------------------------------
__global__ __launch_bounds__(256) void cls_add_kernel(float* __restrict__ scores)
{
    int q    = blockIdx.x;
    int d    = blockIdx.y * 8 + (threadIdx.x >> 5);
    int lane = threadIdx.x & 31;

    const float* qc = g_qry_cls + (size_t)q * DC_;
    const float* dc = g_doc_cls + (size_t)d * DC_;
    float p = 0.f;
#pragma unroll
    for (int k = 0; k < DC_ / 32; k++)
        p += qc[k * 32 + lane] * dc[k * 32 + lane];
#pragma unroll
    for (int off = 16; off > 0; off >>= 1)
        p += __shfl_xor_sync(0xffffffffu, p, off);
    if (lane == 0) scores[q * D_ + d] += p;
}

// ---------------------------------------------------------------------------
// Cross-entropy loss -> g_loss[0]. One block, one warp per query row (D=256).
// ---------------------------------------------------------------------------
__global__ __launch_bounds__(1024) void loss_kernel(
    const float* __restrict__ scores, const int* __restrict__ gs)
{
    __shared__ float wloss[32];
    int tid = threadIdx.x;
    int lane = tid & 31;
    int w = tid >> 5;

    const float* row = scores + (size_t)w * D_;
    float m = -1e30f;
    for (int c = lane; c < D_; c += 32) m = fmaxf(m, row[c]);
#pragma unroll
    for (int off = 16; off > 0; off >>= 1)
        m = fmaxf(m, __shfl_xor_sync(0xffffffffu, m, off));
    float s = 0.f;
    for (int c = lane; c < D_; c += 32) s += expf(row[c] - m);
#pragma unroll
    for (int off = 16; off > 0; off >>= 1)
        s += __shfl_xor_sync(0xffffffffu, s, off);

    int group = 8;
    if (gs) {
        int gv = gs[0];                    // low word OK for i32 and LE i64
        if (gv >= 1 && gv * 31 < D_) group = gv;
    }
    int label = w * group;
    float logp = row[label] - m - logf(s);
    if (lane == 0) wloss[w] = -logp;
    __syncthreads();
    if (tid == 0) {
        float t = 0.f;
        for (int i = 0; i < 32; i++) t += wloss[i];
        g_loss[0] = t / 32.f;
    }
}

// ---------------------------------------------------------------------------
// Output layout by out_size: [loss] | [scores] | [loss, scores, 0-tail]
// ---------------------------------------------------------------------------
__global__ void layout_kernel(float* __restrict__ out, int out_size, int mode)
{
    int i = blockIdx.x * blockDim.x + threadIdx.x;
    if (i >= out_size) return;
    if (mode == 0) {
        if (i == 0) out[0] = g_loss[0];
    } else if (mode == 1) {
        out[i] = (i < Q_ * D_) ? g_scores[i] : 0.f;
    } else {
        if (i == 0) out[0] = g_loss[0];
        else out[i] = (i - 1 < Q_ * D_) ? g_scores[i - 1] : 0.f;
    }
}

// Diagnostic sentinel (mapping failure -> decodable signal, not a crash)
__global__ void diag_kernel(float* out, int missing_mask, int n)
{
    int i = blockIdx.x * blockDim.x + threadIdx.x;
    if (i < n) out[i] = (i == 0) ? (-1.0e6f - (float)missing_mask) : 0.f;
}

// ---------------------------------------------------------------------------
extern "C" void kernel_launch(void* const* d_in, const int* in_sizes, int n_in,
                              void* d_out, int out_size)
{
    const float* qry_hidden = nullptr;   // 786432 elems
    const float* doc_hidden = nullptr;   // 37748736
    const void*  doc_ids    = nullptr;   // 49152
    const float* tok_w      = nullptr;   // 98304
    const float* tok_b      = nullptr;   // 128
    const float* cls_w      = nullptr;   // 589824
    const float* cls_b      = nullptr;   // 768
    const int*   gsize      = nullptr;   // 1
    const void*  cand_a     = nullptr;   // 1024 (ids or mask)
    const void*  cand_b     = nullptr;   // 1024

    long long div = 0;
    for (int i = 0; i < n_in; i++) {
        if (in_sizes[i] == 37748736)  { div = 1; break; }
        if (in_sizes[i] == 150994944) { div = 4; break; }
    }
    if (div == 0) div = 1;

    for (int i = 0; i < n_in; i++) {
        long long sz = (long long)in_sizes[i] / div;
        switch (sz) {
            case 786432:   qry_hidden = (const float*)d_in[i]; break;
            case 37748736: doc_hidden = (const float*)d_in[i]; break;
            case 49152:    doc_ids    = d_in[i];               break;
            case 98304:    tok_w      = (const float*)d_in[i]; break;
            case 128:      tok_b      = (const float*)d_in[i]; break;
            case 589824:   cls_w      = (const float*)d_in[i]; break;
            case 768:      cls_b      = (const float*)d_in[i]; break;
            case 1:        gsize      = (const int*)d_in[i];   break;
            case 1024:
                if (!cand_a) cand_a = d_in[i]; else cand_b = d_in[i];
                break;
            default:
                if (sz == 2 && div == 4) gsize = (const int*)d_in[i];
                break;
        }
    }

    float* out = (float*)d_out;

    int missing = 0;
    if (!qry_hidden) missing |= 1;
    if (!doc_hidden) missing |= 2;
    if (!doc_ids)    missing |= 4;
    if (!tok_w)      missing |= 8;
    if (!tok_b)      missing |= 16;
    if (!cls_w)      missing |= 32;
    if (!cls_b)      missing |= 64;
    if (!cand_a)     missing |= 128;
    if (!cand_b)     missing |= 256;
    if (missing) {
        int n = out_size > 0 ? out_size : 1;
        diag_kernel<<<(n + 255) / 256, 256>>>(out, missing, n);
        return;
    }

    float *doc_reps, *qry_reps, *doc_cls, *qry_cls, *scores;
    cudaGetSymbolAddress((void**)&doc_reps, g_doc_reps);
    cudaGetSymbolAddress((void**)&qry_reps, g_qry_reps);
    cudaGetSymbolAddress((void**)&doc_cls,  g_doc_cls);
    cudaGetSymbolAddress((void**)&qry_cls,  g_qry_cls);
    cudaGetSymbolAddress((void**)&scores,   g_scores);

    // 1) all four projections in ONE wave
    mega_gemm<<<NB_TOTAL, 256>>>(doc_hidden, qry_hidden,
                                 tok_w, tok_b, cls_w, cls_b,
                                 doc_reps, qry_reps, doc_cls, qry_cls);
    // 2) sparse exact-match token scores -> g_scores
    {
        dim3 grid(Q_, D_ / 8);
        tok_kernel<<<grid, 128>>>(cand_a, cand_b, (const int*)doc_ids, scores);
    }
    // 3) scores += cls dot products (wide, coalesced)
    {
        dim3 grid(Q_, D_ / 8);
        cls_add_kernel<<<grid, 256>>>(scores);
    }
    // 4) loss -> g_loss
    loss_kernel<<<1, 1024>>>(scores, gsize);
    // 5) lay out per out_size (expected 1 + 32*256 = 8193)
    int mode = (out_size == 1) ? 0 : (out_size == Q_ * D_) ? 1 : 2;
    layout_kernel<<<(out_size + 255) / 256, 256>>>(out, out_size, mode);
}

// round 11
// speedup vs baseline: 3.9600x; 1.5707x over previous
#include <cuda_runtime.h>

#define Q_  32
#define LQ_ 32
#define D_  256
#define LD_ 192
#define H_  768
#define DT_ 128
#define DC_ 768

// Scratch (allocation-free: __device__ globals)
__device__ float g_doc_reps[(size_t)D_ * LD_ * DT_];   // 25.2 MB
__device__ float g_qry_reps[(size_t)Q_ * LQ_ * DT_];
__device__ float g_doc_cls[(size_t)D_ * DC_];
__device__ float g_qry_cls[(size_t)Q_ * DC_];
__device__ float g_scores[(size_t)Q_ * D_];
__device__ float g_loss[1];

// Mega-GEMM block ranges (128x128 output tiles)
#define NB_DOCREP 384                      // 49152/128 m-tiles, N=128
#define NB_QRYREP 8                        // 1024/128 m-tiles
#define NB_DOCCLS 12                       // 2 m-tiles x 6 n-tiles
#define NB_QRYCLS 6                        // 1 m-tile  x 6 n-tiles
#define NB_TOTAL  (NB_DOCREP + NB_QRYREP + NB_DOCCLS + NB_QRYCLS)

__device__ __forceinline__ unsigned f2tf32(float f) {
    unsigned u;
    asm("cvt.rna.tf32.f32 %0, %1;" : "=r"(u) : "f"(f));
    return u;
}

// ---------------------------------------------------------------------------
// Tensor-core mega-GEMM (tf32 mma.sync.m16n8k8, fp32 accum).
// One launch covers all four projections. BM=BN=128, BK=16, 256 thr = 8 warps
// in a 2x4 grid; each warp owns a 64x32 tile = 4x4 m16n8 mma tiles.
//   C[m,n] = act( sum_k A[m*lda+k] * B[k*ldb+n] + bias[n] )
// ---------------------------------------------------------------------------
__global__ __launch_bounds__(256) void mega_gemm_tc(
    const float* __restrict__ doc_hidden,
    const float* __restrict__ qry_hidden,
    const float* __restrict__ tok_w, const float* __restrict__ tok_b,
    const float* __restrict__ cls_w, const float* __restrict__ cls_b,
    float* __restrict__ doc_reps, float* __restrict__ qry_reps,
    float* __restrict__ doc_cls,  float* __restrict__ qry_cls)
{
    const int BK = 16;
    __shared__ unsigned As[128][BK + 4];   // [m][k], +4 pad: conflict-free frags
    __shared__ unsigned Bs[BK][128 + 4];   // [k][n], +4 pad

    // --- segment dispatch ---
    const float* A; const float* B; const float* bias; float* C;
    int lda, ldb, ldc, M, bm, bn, relu;
    int blk = blockIdx.x;
    if (blk < NB_DOCREP) {
        A = doc_hidden; lda = H_;        B = tok_w; ldb = DT_; bias = tok_b;
        C = doc_reps;   ldc = DT_;       M = D_ * LD_;
        bm = blk * 128; bn = 0;          relu = 1;
    } else if (blk < NB_DOCREP + NB_QRYREP) {
        int t = blk - NB_DOCREP;
        A = qry_hidden; lda = H_;        B = tok_w; ldb = DT_; bias = tok_b;
        C = qry_reps;   ldc = DT_;       M = Q_ * LQ_;
        bm = t * 128;   bn = 0;          relu = 1;
    } else if (blk < NB_DOCREP + NB_QRYREP + NB_DOCCLS) {
        int t = blk - NB_DOCREP - NB_QRYREP;
        A = doc_hidden; lda = LD_ * H_;  B = cls_w; ldb = DC_; bias = cls_b;
        C = doc_cls;    ldc = DC_;       M = D_;
        bm = (t % 2) * 128; bn = (t / 2) * 128; relu = 0;
    } else {
        int t = blk - NB_DOCREP - NB_QRYREP - NB_DOCCLS;
        A = qry_hidden; lda = LQ_ * H_;  B = cls_w; ldb = DC_; bias = cls_b;
        C = qry_cls;    ldc = DC_;       M = Q_;
        bm = 0;         bn = t * 128;    relu = 0;
    }

    int tid  = threadIdx.x;
    int lane = tid & 31;
    int wid  = tid >> 5;
    int warp_m = (wid >> 2) * 64;     // 0 | 64
    int warp_n = (wid & 3) * 32;      // 0 | 32 | 64 | 96
    int grp = lane >> 2;              // 0..7
    int tig = lane & 3;               // 0..3

    float c[4][4][4];
#pragma unroll
    for (int mt = 0; mt < 4; mt++)
#pragma unroll
        for (int nt = 0; nt < 4; nt++)
#pragma unroll
            for (int r = 0; r < 4; r++) c[mt][nt][r] = 0.f;

    int a_row = tid >> 1;             // 0..127
    int a_col = (tid & 1) * 8;        // 0 | 8
    int b_row = tid >> 4;             // 0..15
    int b_col = (tid & 15) * 8;       // 0..120

    for (int k0 = 0; k0 < H_; k0 += BK) {
        // --- stage A tile (M-guarded, zero fill), convert to tf32 bits ---
        float va[8];
        if (bm + a_row < M) {
            float4 t0 = *reinterpret_cast<const float4*>(A + (size_t)(bm + a_row) * lda + k0 + a_col);
            float4 t1 = *reinterpret_cast<const float4*>(A + (size_t)(bm + a_row) * lda + k0 + a_col + 4);
            va[0]=t0.x; va[1]=t0.y; va[2]=t0.z; va[3]=t0.w;
            va[4]=t1.x; va[5]=t1.y; va[6]=t1.z; va[7]=t1.w;
        } else {
#pragma unroll
            for (int j = 0; j < 8; j++) va[j] = 0.f;
        }
        *reinterpret_cast<uint4*>(&As[a_row][a_col]) =
            make_uint4(f2tf32(va[0]), f2tf32(va[1]), f2tf32(va[2]), f2tf32(va[3]));
        *reinterpret_cast<uint4*>(&As[a_row][a_col + 4]) =
            make_uint4(f2tf32(va[4]), f2tf32(va[5]), f2tf32(va[6]), f2tf32(va[7]));

        // --- stage B tile ---
        {
            float4 t0 = *reinterpret_cast<const float4*>(B + (size_t)(k0 + b_row) * ldb + bn + b_col);
            float4 t1 = *reinterpret_cast<const float4*>(B + (size_t)(k0 + b_row) * ldb + bn + b_col + 4);
            *reinterpret_cast<uint4*>(&Bs[b_row][b_col]) =
                make_uint4(f2tf32(t0.x), f2tf32(t0.y), f2tf32(t0.z), f2tf32(t0.w));
            *reinterpret_cast<uint4*>(&Bs[b_row][b_col + 4]) =
                make_uint4(f2tf32(t1.x), f2tf32(t1.y), f2tf32(t1.z), f2tf32(t1.w));
        }
        __syncthreads();

#pragma unroll
        for (int ks = 0; ks < 2; ks++) {
            int kb = ks * 8;
            unsigned bf[4][2];
#pragma unroll
            for (int nt = 0; nt < 4; nt++) {
                int n = warp_n + nt * 8 + grp;
                bf[nt][0] = Bs[kb + tig][n];
                bf[nt][1] = Bs[kb + tig + 4][n];
            }
#pragma unroll
            for (int mt = 0; mt < 4; mt++) {
                int m = warp_m + mt * 16 + grp;
                unsigned a0 = As[m][kb + tig];
                unsigned a1 = As[m + 8][kb + tig];
                unsigned a2 = As[m][kb + tig + 4];
                unsigned a3 = As[m + 8][kb + tig + 4];
#pragma unroll
                for (int nt = 0; nt < 4; nt++) {
                    asm volatile(
                        "mma.sync.aligned.m16n8k8.row.col.f32.tf32.tf32.f32 "
                        "{%0,%1,%2,%3}, {%4,%5,%6,%7}, {%8,%9}, {%0,%1,%2,%3};\n"
                        : "+f"(c[mt][nt][0]), "+f"(c[mt][nt][1]),
                          "+f"(c[mt][nt][2]), "+f"(c[mt][nt][3])
                        : "r"(a0), "r"(a1), "r"(a2), "r"(a3),
                          "r"(bf[nt][0]), "r"(bf[nt][1]));
                }
            }
        }
        __syncthreads();
    }

    // --- epilogue: bias (+relu), float2 stores ---
#pragma unroll
    for (int mt = 0; mt < 4; mt++) {
#pragma unroll
        for (int nt = 0; nt < 4; nt++) {
            int m0 = bm + warp_m + mt * 16 + grp;
            int n0 = bn + warp_n + nt * 8 + tig * 2;
            float b0 = bias[n0], b1 = bias[n0 + 1];
            if (m0 < M) {
                float v0 = c[mt][nt][0] + b0;
                float v1 = c[mt][nt][1] + b1;
                if (relu) { v0 = fmaxf(v0, 0.f); v1 = fmaxf(v1, 0.f); }
                *reinterpret_cast<float2*>(C + (size_t)m0 * ldc + n0) = make_float2(v0, v1);
            }
            if (m0 + 8 < M) {
                float v2 = c[mt][nt][2] + b0;
                float v3 = c[mt][nt][3] + b1;
                if (relu) { v2 = fmaxf(v2, 0.f); v3 = fmaxf(v3, 0.f); }
                *reinterpret_cast<float2*>(C + (size_t)(m0 + 8) * ldc + n0) = make_float2(v2, v3);
            }
        }
    }
}

// Disambiguate the two 1024-element inputs on device: the attention mask is
// all exactly 1.0f (bits 0x3F800000); input ids are int32 < 1000.
__device__ __forceinline__ bool is_mask_arr(const void* p) {
    const unsigned* u = (const unsigned*)p;
    return u[0] == 0x3F800000u && u[1] == 0x3F800000u && u[2] == 0x3F800000u;
}

// ---------------------------------------------------------------------------
// Sparse exact-match token scoring. Block = (q, chunk of 8 docs).
// g_scores[q,d] = sum_{i=1..LQ-1} qmask[q,i] *
//                 max_{j: doc_ids[d,j]==qry_ids[q,i]} dot(qrep[q,i], drep[d,j])
// ---------------------------------------------------------------------------
__global__ __launch_bounds__(128) void tok_kernel(
    const void* __restrict__ cand_a, const void* __restrict__ cand_b,
    const int* __restrict__ dids_g,
    float* __restrict__ scores)
{
    bool a_mask = is_mask_arr(cand_a);
    const int*   qids_g  = (const int*)  (a_mask ? cand_b : cand_a);
    const float* qmask_g = (const float*)(a_mask ? cand_a : cand_b);

    __shared__ float qs[LQ_][DT_];     // 16 KB
    __shared__ int   s_qids[LQ_];
    __shared__ float s_qmask[LQ_];
    __shared__ int   s_dids[LD_];
    __shared__ float warp_acc[4];

    int q   = blockIdx.x;
    int d0  = blockIdx.y * 8;
    int tid = threadIdx.x;
    int lane = tid & 31;
    int w    = tid >> 5;

    for (int t = tid; t < LQ_ * DT_; t += 128)
        qs[t / DT_][t % DT_] = g_qry_reps[(size_t)q * LQ_ * DT_ + t];
    if (tid < LQ_) {
        s_qids[tid]  = qids_g[q * LQ_ + tid];
        s_qmask[tid] = qmask_g[q * LQ_ + tid];
    }
    __syncthreads();

    for (int dd = 0; dd < 8; dd++) {
        int d = d0 + dd;
        for (int t = tid; t < LD_; t += 128)
            s_dids[t] = dids_g[d * LD_ + t];
        __syncthreads();

        const float* drep = g_doc_reps + (size_t)d * LD_ * DT_;
        float acc = 0.f;

        for (int i = 1 + w; i < LQ_; i += 4) {
            int tok = s_qids[i];
            float best = 0.f;
#pragma unroll
            for (int jb = 0; jb < LD_; jb += 32) {
                int j = jb + lane;
                unsigned mask = __ballot_sync(0xffffffffu, s_dids[j] == tok);
                while (mask) {
                    int jj = jb + (__ffs(mask) - 1);
                    mask &= mask - 1;
                    const float* dr = drep + (size_t)jj * DT_;
                    float p = qs[i][lane]      * dr[lane]
                            + qs[i][lane + 32] * dr[lane + 32]
                            + qs[i][lane + 64] * dr[lane + 64]
                            + qs[i][lane + 96] * dr[lane + 96];
#pragma unroll
                    for (int off = 16; off > 0; off >>= 1)
                        p += __shfl_xor_sync(0xffffffffu, p, off);
                    best = fmaxf(best, p);
                }
            }
            acc += best * s_qmask[i];
        }

        if (lane == 0) warp_acc[w] = acc;
        __syncthreads();
        if (tid == 0)
            scores[q * D_ + d] = warp_acc[0] + warp_acc[1] + warp_acc[2] + warp_acc[3];
        __syncthreads();
    }
}

// ---------------------------------------------------------------------------
// scores[q,d] += dot(qry_cls[q,:], doc_cls[d,:]).
// ---------------------------------------------------------------------------
__global__ __launch_bounds__(256) void cls_add_kernel(float* __restrict__ scores)
{
    int q    = blockIdx.x;
    int d    = blockIdx.y * 8 + (threadIdx.x >> 5);
    int lane = threadIdx.x & 31;

    const float* qc = g_qry_cls + (size_t)q * DC_;
    const float* dc = g_doc_cls + (size_t)d * DC_;
    float p = 0.f;
#pragma unroll
    for (int k = 0; k < DC_ / 32; k++)
        p += qc[k * 32 + lane] * dc[k * 32 + lane];
#pragma unroll
    for (int off = 16; off > 0; off >>= 1)
        p += __shfl_xor_sync(0xffffffffu, p, off);
    if (lane == 0) scores[q * D_ + d] += p;
}

// ---------------------------------------------------------------------------
// Cross-entropy loss -> g_loss[0].
// ---------------------------------------------------------------------------
__global__ __launch_bounds__(1024) void loss_kernel(
    const float* __restrict__ scores, const int* __restrict__ gs)
{
    __shared__ float wloss[32];
    int tid = threadIdx.x;
    int lane = tid & 31;
    int w = tid >> 5;

    const float* row = scores + (size_t)w * D_;
    float m = -1e30f;
    for (int c = lane; c < D_; c += 32) m = fmaxf(m, row[c]);
#pragma unroll
    for (int off = 16; off > 0; off >>= 1)
        m = fmaxf(m, __shfl_xor_sync(0xffffffffu, m, off));
    float s = 0.f;
    for (int c = lane; c < D_; c += 32) s += expf(row[c] - m);
#pragma unroll
    for (int off = 16; off > 0; off >>= 1)
        s += __shfl_xor_sync(0xffffffffu, s, off);

    int group = 8;
    if (gs) {
        int gv = gs[0];
        if (gv >= 1 && gv * 31 < D_) group = gv;
    }
    int label = w * group;
    float logp = row[label] - m - logf(s);
    if (lane == 0) wloss[w] = -logp;
    __syncthreads();
    if (tid == 0) {
        float t = 0.f;
        for (int i = 0; i < 32; i++) t += wloss[i];
        g_loss[0] = t / 32.f;
    }
}

// ---------------------------------------------------------------------------
// Output layout by out_size: [loss] | [scores] | [loss, scores, 0-tail]
// ---------------------------------------------------------------------------
__global__ void layout_kernel(float* __restrict__ out, int out_size, int mode)
{
    int i = blockIdx.x * blockDim.x + threadIdx.x;
    if (i >= out_size) return;
    if (mode == 0) {
        if (i == 0) out[0] = g_loss[0];
    } else if (mode == 1) {
        out[i] = (i < Q_ * D_) ? g_scores[i] : 0.f;
    } else {
        if (i == 0) out[0] = g_loss[0];
        else out[i] = (i - 1 < Q_ * D_) ? g_scores[i - 1] : 0.f;
    }
}

// Diagnostic sentinel (mapping failure -> decodable signal, not a crash)
__global__ void diag_kernel(float* out, int missing_mask, int n)
{
    int i = blockIdx.x * blockDim.x + threadIdx.x;
    if (i < n) out[i] = (i == 0) ? (-1.0e6f - (float)missing_mask) : 0.f;
}

// ---------------------------------------------------------------------------
extern "C" void kernel_launch(void* const* d_in, const int* in_sizes, int n_in,
                              void* d_out, int out_size)
{
    const float* qry_hidden = nullptr;   // 786432 elems
    const float* doc_hidden = nullptr;   // 37748736
    const void*  doc_ids    = nullptr;   // 49152
    const float* tok_w      = nullptr;   // 98304
    const float* tok_b      = nullptr;   // 128
    const float* cls_w      = nullptr;   // 589824
    const float* cls_b      = nullptr;   // 768
    const int*   gsize      = nullptr;   // 1
    const void*  cand_a     = nullptr;   // 1024 (ids or mask)
    const void*  cand_b     = nullptr;   // 1024

    long long div = 0;
    for (int i = 0; i < n_in; i++) {
        if (in_sizes[i] == 37748736)  { div = 1; break; }
        if (in_sizes[i] == 150994944) { div = 4; break; }
    }
    if (div == 0) div = 1;

    for (int i = 0; i < n_in; i++) {
        long long sz = (long long)in_sizes[i] / div;
        switch (sz) {
            case 786432:   qry_hidden = (const float*)d_in[i]; break;
            case 37748736: doc_hidden = (const float*)d_in[i]; break;
            case 49152:    doc_ids    = d_in[i];               break;
            case 98304:    tok_w      = (const float*)d_in[i]; break;
            case 128:      tok_b      = (const float*)d_in[i]; break;
            case 589824:   cls_w      = (const float*)d_in[i]; break;
            case 768:      cls_b      = (const float*)d_in[i]; break;
            case 1:        gsize      = (const int*)d_in[i];   break;
            case 1024:
                if (!cand_a) cand_a = d_in[i]; else cand_b = d_in[i];
                break;
            default:
                if (sz == 2 && div == 4) gsize = (const int*)d_in[i];
                break;
        }
    }

    float* out = (float*)d_out;

    int missing = 0;
    if (!qry_hidden) missing |= 1;
    if (!doc_hidden) missing |= 2;
    if (!doc_ids)    missing |= 4;
    if (!tok_w)      missing |= 8;
    if (!tok_b)      missing |= 16;
    if (!cls_w)      missing |= 32;
    if (!cls_b)      missing |= 64;
    if (!cand_a)     missing |= 128;
    if (!cand_b)     missing |= 256;
    if (missing) {
        int n = out_size > 0 ? out_size : 1;
        diag_kernel<<<(n + 255) / 256, 256>>>(out, missing, n);
        return;
    }

    float *doc_reps, *qry_reps, *doc_cls, *qry_cls, *scores;
    cudaGetSymbolAddress((void**)&doc_reps, g_doc_reps);
    cudaGetSymbolAddress((void**)&qry_reps, g_qry_reps);
    cudaGetSymbolAddress((void**)&doc_cls,  g_doc_cls);
    cudaGetSymbolAddress((void**)&qry_cls,  g_qry_cls);
    cudaGetSymbolAddress((void**)&scores,   g_scores);

    // 1) all four projections in ONE tensor-core wave
    mega_gemm_tc<<<NB_TOTAL, 256>>>(doc_hidden, qry_hidden,
                                    tok_w, tok_b, cls_w, cls_b,
                                    doc_reps, qry_reps, doc_cls, qry_cls);
    // 2) sparse exact-match token scores -> g_scores
    {
        dim3 grid(Q_, D_ / 8);
        tok_kernel<<<grid, 128>>>(cand_a, cand_b, (const int*)doc_ids, scores);
    }
    // 3) scores += cls dot products
    {
        dim3 grid(Q_, D_ / 8);
        cls_add_kernel<<<grid, 256>>>(scores);
    }
    // 4) loss -> g_loss
    loss_kernel<<<1, 1024>>>(scores, gsize);
    // 5) lay out per out_size (expected 1 + 32*256 = 8193)
    int mode = (out_size == 1) ? 0 : (out_size == Q_ * D_) ? 1 : 2;
    layout_kernel<<<(out_size + 255) / 256, 256>>>(out, out_size, mode);
}

// round 12
// speedup vs baseline: 5.5240x; 1.3949x over previous
#include <cuda_runtime.h>

#define Q_  32
#define LQ_ 32
#define D_  256
#define LD_ 192
#define H_  768
#define DT_ 128
#define DC_ 768

// Scratch (allocation-free: __device__ globals)
__device__ float g_doc_reps[(size_t)D_ * LD_ * DT_];   // 25.2 MB
__device__ float g_qry_reps[(size_t)Q_ * LQ_ * DT_];
__device__ float g_doc_cls[(size_t)D_ * DC_];
__device__ float g_qry_cls[(size_t)Q_ * DC_];
__device__ float g_scores[(size_t)Q_ * D_];

// Mega-GEMM block ranges (128x128 output tiles)
#define NB_DOCREP 384
#define NB_QRYREP 8
#define NB_DOCCLS 12
#define NB_QRYCLS 6
#define NB_TOTAL  (NB_DOCREP + NB_QRYREP + NB_DOCCLS + NB_QRYCLS)

__device__ __forceinline__ unsigned f2tf32(float f) {
    unsigned u;
    asm("cvt.rna.tf32.f32 %0, %1;" : "=r"(u) : "f"(f));
    return u;
}

// ---------------------------------------------------------------------------
// Tensor-core mega-GEMM (tf32 mma.sync.m16n8k8, fp32 accum), 2-stage
// double-buffered pipeline: load slab i+1 to regs while MMA-ing slab i.
// BM=BN=128, BK=16, 256 thr = 8 warps (2x4), warp tile 64x32.
// ---------------------------------------------------------------------------
__global__ __launch_bounds__(256) void mega_gemm_tc(
    const float* __restrict__ doc_hidden,
    const float* __restrict__ qry_hidden,
    const float* __restrict__ tok_w, const float* __restrict__ tok_b,
    const float* __restrict__ cls_w, const float* __restrict__ cls_b,
    float* __restrict__ doc_reps, float* __restrict__ qry_reps,
    float* __restrict__ doc_cls,  float* __restrict__ qry_cls)
{
    const int BK = 16;
    const int NIT = H_ / BK;                 // 48
    __shared__ unsigned As[2][128][BK + 4];  // [buf][m][k]
    __shared__ unsigned Bs[2][BK][128 + 4];  // [buf][k][n]

    // --- segment dispatch ---
    const float* A; const float* B; const float* bias; float* C;
    int lda, ldb, ldc, M, bm, bn, relu;
    int blk = blockIdx.x;
    if (blk < NB_DOCREP) {
        A = doc_hidden; lda = H_;        B = tok_w; ldb = DT_; bias = tok_b;
        C = doc_reps;   ldc = DT_;       M = D_ * LD_;
        bm = blk * 128; bn = 0;          relu = 1;
    } else if (blk < NB_DOCREP + NB_QRYREP) {
        int t = blk - NB_DOCREP;
        A = qry_hidden; lda = H_;        B = tok_w; ldb = DT_; bias = tok_b;
        C = qry_reps;   ldc = DT_;       M = Q_ * LQ_;
        bm = t * 128;   bn = 0;          relu = 1;
    } else if (blk < NB_DOCREP + NB_QRYREP + NB_DOCCLS) {
        int t = blk - NB_DOCREP - NB_QRYREP;
        A = doc_hidden; lda = LD_ * H_;  B = cls_w; ldb = DC_; bias = cls_b;
        C = doc_cls;    ldc = DC_;       M = D_;
        bm = (t % 2) * 128; bn = (t / 2) * 128; relu = 0;
    } else {
        int t = blk - NB_DOCREP - NB_QRYREP - NB_DOCCLS;
        A = qry_hidden; lda = LQ_ * H_;  B = cls_w; ldb = DC_; bias = cls_b;
        C = qry_cls;    ldc = DC_;       M = Q_;
        bm = 0;         bn = t * 128;    relu = 0;
    }

    int tid  = threadIdx.x;
    int lane = tid & 31;
    int wid  = tid >> 5;
    int warp_m = (wid >> 2) * 64;
    int warp_n = (wid & 3) * 32;
    int grp = lane >> 2;
    int tig = lane & 3;

    float c[4][4][4];
#pragma unroll
    for (int mt = 0; mt < 4; mt++)
#pragma unroll
        for (int nt = 0; nt < 4; nt++)
#pragma unroll
            for (int r = 0; r < 4; r++) c[mt][nt][r] = 0.f;

    int a_row = tid >> 1;             // 0..127
    int a_col = (tid & 1) * 8;        // 0 | 8
    int b_row = tid >> 4;             // 0..15
    int b_col = (tid & 15) * 8;       // 0..120
    bool a_ok = (bm + a_row < M);
    const float* a_src = A + (size_t)(bm + a_row) * lda + a_col;
    const float* b_src = B + (size_t)b_row * ldb + bn + b_col;

    float va[8], vb[8];
    // --- prologue: load slab 0 ---
    if (a_ok) {
        float4 t0 = *reinterpret_cast<const float4*>(a_src);
        float4 t1 = *reinterpret_cast<const float4*>(a_src + 4);
        va[0]=t0.x; va[1]=t0.y; va[2]=t0.z; va[3]=t0.w;
        va[4]=t1.x; va[5]=t1.y; va[6]=t1.z; va[7]=t1.w;
    } else {
#pragma unroll
        for (int j = 0; j < 8; j++) va[j] = 0.f;
    }
    {
        float4 t0 = *reinterpret_cast<const float4*>(b_src);
        float4 t1 = *reinterpret_cast<const float4*>(b_src + 4);
        vb[0]=t0.x; vb[1]=t0.y; vb[2]=t0.z; vb[3]=t0.w;
        vb[4]=t1.x; vb[5]=t1.y; vb[6]=t1.z; vb[7]=t1.w;
    }
    *reinterpret_cast<uint4*>(&As[0][a_row][a_col]) =
        make_uint4(f2tf32(va[0]), f2tf32(va[1]), f2tf32(va[2]), f2tf32(va[3]));
    *reinterpret_cast<uint4*>(&As[0][a_row][a_col + 4]) =
        make_uint4(f2tf32(va[4]), f2tf32(va[5]), f2tf32(va[6]), f2tf32(va[7]));
    *reinterpret_cast<uint4*>(&Bs[0][b_row][b_col]) =
        make_uint4(f2tf32(vb[0]), f2tf32(vb[1]), f2tf32(vb[2]), f2tf32(vb[3]));
    *reinterpret_cast<uint4*>(&Bs[0][b_row][b_col + 4]) =
        make_uint4(f2tf32(vb[4]), f2tf32(vb[5]), f2tf32(vb[6]), f2tf32(vb[7]));
    __syncthreads();

    for (int it = 0; it < NIT; it++) {
        int cur = it & 1;
        // --- issue next-slab global loads early (latency overlap) ---
        if (it + 1 < NIT) {
            int k0 = (it + 1) * BK;
            if (a_ok) {
                float4 t0 = *reinterpret_cast<const float4*>(a_src + k0);
                float4 t1 = *reinterpret_cast<const float4*>(a_src + k0 + 4);
                va[0]=t0.x; va[1]=t0.y; va[2]=t0.z; va[3]=t0.w;
                va[4]=t1.x; va[5]=t1.y; va[6]=t1.z; va[7]=t1.w;
            }
            float4 t0 = *reinterpret_cast<const float4*>(b_src + (size_t)k0 * ldb);
            float4 t1 = *reinterpret_cast<const float4*>(b_src + (size_t)k0 * ldb + 4);
            vb[0]=t0.x; vb[1]=t0.y; vb[2]=t0.z; vb[3]=t0.w;
            vb[4]=t1.x; vb[5]=t1.y; vb[6]=t1.z; vb[7]=t1.w;
        }

        // --- MMA on current buffer ---
#pragma unroll
        for (int ks = 0; ks < 2; ks++) {
            int kb = ks * 8;
            unsigned bf[4][2];
#pragma unroll
            for (int nt = 0; nt < 4; nt++) {
                int n = warp_n + nt * 8 + grp;
                bf[nt][0] = Bs[cur][kb + tig][n];
                bf[nt][1] = Bs[cur][kb + tig + 4][n];
            }
#pragma unroll
            for (int mt = 0; mt < 4; mt++) {
                int m = warp_m + mt * 16 + grp;
                unsigned a0 = As[cur][m][kb + tig];
                unsigned a1 = As[cur][m + 8][kb + tig];
                unsigned a2 = As[cur][m][kb + tig + 4];
                unsigned a3 = As[cur][m + 8][kb + tig + 4];
#pragma unroll
                for (int nt = 0; nt < 4; nt++) {
                    asm volatile(
                        "mma.sync.aligned.m16n8k8.row.col.f32.tf32.tf32.f32 "
                        "{%0,%1,%2,%3}, {%4,%5,%6,%7}, {%8,%9}, {%0,%1,%2,%3};\n"
                        : "+f"(c[mt][nt][0]), "+f"(c[mt][nt][1]),
                          "+f"(c[mt][nt][2]), "+f"(c[mt][nt][3])
                        : "r"(a0), "r"(a1), "r"(a2), "r"(a3),
                          "r"(bf[nt][0]), "r"(bf[nt][1]));
                }
            }
        }

        // --- convert & stage next slab into the other buffer ---
        if (it + 1 < NIT) {
            int nxt = 1 - cur;
            *reinterpret_cast<uint4*>(&As[nxt][a_row][a_col]) =
                make_uint4(f2tf32(va[0]), f2tf32(va[1]), f2tf32(va[2]), f2tf32(va[3]));
            *reinterpret_cast<uint4*>(&As[nxt][a_row][a_col + 4]) =
                make_uint4(f2tf32(va[4]), f2tf32(va[5]), f2tf32(va[6]), f2tf32(va[7]));
            *reinterpret_cast<uint4*>(&Bs[nxt][b_row][b_col]) =
                make_uint4(f2tf32(vb[0]), f2tf32(vb[1]), f2tf32(vb[2]), f2tf32(vb[3]));
            *reinterpret_cast<uint4*>(&Bs[nxt][b_row][b_col + 4]) =
                make_uint4(f2tf32(vb[4]), f2tf32(vb[5]), f2tf32(vb[6]), f2tf32(vb[7]));
        }
        __syncthreads();
    }

    // --- epilogue: bias (+relu), float2 stores ---
#pragma unroll
    for (int mt = 0; mt < 4; mt++) {
#pragma unroll
        for (int nt = 0; nt < 4; nt++) {
            int m0 = bm + warp_m + mt * 16 + grp;
            int n0 = bn + warp_n + nt * 8 + tig * 2;
            float b0 = bias[n0], b1 = bias[n0 + 1];
            if (m0 < M) {
                float v0 = c[mt][nt][0] + b0;
                float v1 = c[mt][nt][1] + b1;
                if (relu) { v0 = fmaxf(v0, 0.f); v1 = fmaxf(v1, 0.f); }
                *reinterpret_cast<float2*>(C + (size_t)m0 * ldc + n0) = make_float2(v0, v1);
            }
            if (m0 + 8 < M) {
                float v2 = c[mt][nt][2] + b0;
                float v3 = c[mt][nt][3] + b1;
                if (relu) { v2 = fmaxf(v2, 0.f); v3 = fmaxf(v3, 0.f); }
                *reinterpret_cast<float2*>(C + (size_t)(m0 + 8) * ldc + n0) = make_float2(v2, v3);
            }
        }
    }
}

// Disambiguate the two 1024-element inputs on device.
__device__ __forceinline__ bool is_mask_arr(const void* p) {
    const unsigned* u = (const unsigned*)p;
    return u[0] == 0x3F800000u && u[1] == 0x3F800000u && u[2] == 0x3F800000u;
}

// ---------------------------------------------------------------------------
// Sparse exact-match token scoring + fused cls dot. Block = (q, 8 docs).
// scores[q,d] = sum_{i>=1} qmask[q,i] *
//               max_{j: dids[d,j]==qids[q,i]} dot(qrep[q,i], drep[d,j])
//             + dot(qry_cls[q], doc_cls[d])
// ---------------------------------------------------------------------------
__global__ __launch_bounds__(128) void tok_kernel(
    const void* __restrict__ cand_a, const void* __restrict__ cand_b,
    const int* __restrict__ dids_g,
    float* __restrict__ scores)
{
    bool a_mask = is_mask_arr(cand_a);
    const int*   qids_g  = (const int*)  (a_mask ? cand_b : cand_a);
    const float* qmask_g = (const float*)(a_mask ? cand_a : cand_b);

    __shared__ float qs[LQ_][DT_];     // 16 KB
    __shared__ float qcls[DC_];        // 3 KB (this q's cls vector)
    __shared__ int   s_qids[LQ_];
    __shared__ float s_qmask[LQ_];
    __shared__ int   s_dids[LD_];
    __shared__ float warp_acc[4];
    __shared__ float warp_cls[4];

    int q   = blockIdx.x;
    int d0  = blockIdx.y * 8;
    int tid = threadIdx.x;
    int lane = tid & 31;
    int w    = tid >> 5;

    for (int t = tid; t < LQ_ * DT_; t += 128)
        qs[t / DT_][t % DT_] = g_qry_reps[(size_t)q * LQ_ * DT_ + t];
    for (int t = tid; t < DC_; t += 128)
        qcls[t] = g_qry_cls[(size_t)q * DC_ + t];
    if (tid < LQ_) {
        s_qids[tid]  = qids_g[q * LQ_ + tid];
        s_qmask[tid] = qmask_g[q * LQ_ + tid];
    }
    __syncthreads();

    for (int dd = 0; dd < 8; dd++) {
        int d = d0 + dd;
        for (int t = tid; t < LD_; t += 128)
            s_dids[t] = dids_g[d * LD_ + t];
        __syncthreads();

        const float* drep = g_doc_reps + (size_t)d * LD_ * DT_;
        float acc = 0.f;

        for (int i = 1 + w; i < LQ_; i += 4) {
            int tok = s_qids[i];
            float best = 0.f;
#pragma unroll
            for (int jb = 0; jb < LD_; jb += 32) {
                int j = jb + lane;
                unsigned mask = __ballot_sync(0xffffffffu, s_dids[j] == tok);
                while (mask) {
                    int jj = jb + (__ffs(mask) - 1);
                    mask &= mask - 1;
                    const float* dr = drep + (size_t)jj * DT_;
                    float p = qs[i][lane]      * dr[lane]
                            + qs[i][lane + 32] * dr[lane + 32]
                            + qs[i][lane + 64] * dr[lane + 64]
                            + qs[i][lane + 96] * dr[lane + 96];
#pragma unroll
                    for (int off = 16; off > 0; off >>= 1)
                        p += __shfl_xor_sync(0xffffffffu, p, off);
                    best = fmaxf(best, p);
                }
            }
            acc += best * s_qmask[i];
        }

        // fused cls dot for this (q, d)
        const float* dcls = g_doc_cls + (size_t)d * DC_;
        float pc = 0.f;
#pragma unroll
        for (int k = 0; k < DC_ / 128; k++)
            pc += qcls[k * 128 + tid] * dcls[k * 128 + tid];
#pragma unroll
        for (int off = 16; off > 0; off >>= 1)
            pc += __shfl_xor_sync(0xffffffffu, pc, off);

        if (lane == 0) { warp_acc[w] = acc; warp_cls[w] = pc; }
        __syncthreads();
        if (tid == 0)
            scores[q * D_ + d] = warp_acc[0] + warp_acc[1] + warp_acc[2] + warp_acc[3]
                               + warp_cls[0] + warp_cls[1] + warp_cls[2] + warp_cls[3];
        __syncthreads();
    }
}

// ---------------------------------------------------------------------------
// Fused loss + output layout. One block of 1024: 32 warps compute the 32
// row-softmax losses, then all threads write out[] per out_size convention.
// ---------------------------------------------------------------------------
__global__ __launch_bounds__(1024) void loss_layout_kernel(
    const float* __restrict__ scores, const int* __restrict__ gs,
    float* __restrict__ out, int out_size, int mode)
{
    __shared__ float wloss[32];
    __shared__ float s_loss;
    int tid = threadIdx.x;
    int lane = tid & 31;
    int w = tid >> 5;

    const float* row = scores + (size_t)w * D_;
    float m = -1e30f;
    for (int c = lane; c < D_; c += 32) m = fmaxf(m, row[c]);
#pragma unroll
    for (int off = 16; off > 0; off >>= 1)
        m = fmaxf(m, __shfl_xor_sync(0xffffffffu, m, off));
    float s = 0.f;
    for (int c = lane; c < D_; c += 32) s += expf(row[c] - m);
#pragma unroll
    for (int off = 16; off > 0; off >>= 1)
        s += __shfl_xor_sync(0xffffffffu, s, off);

    int group = 8;
    if (gs) {
        int gv = gs[0];
        if (gv >= 1 && gv * 31 < D_) group = gv;
    }
    int label = w * group;
    float logp = row[label] - m - logf(s);
    if (lane == 0) wloss[w] = -logp;
    __syncthreads();
    if (tid == 0) {
        float t = 0.f;
        for (int i = 0; i < 32; i++) t += wloss[i];
        s_loss = t / 32.f;
    }
    __syncthreads();

    float loss = s_loss;
    for (int i = tid; i < out_size; i += 1024) {
        if (mode == 0) {
            if (i == 0) out[0] = loss;
        } else if (mode == 1) {
            out[i] = (i < Q_ * D_) ? scores[i] : 0.f;
        } else {
            if (i == 0) out[0] = loss;
            else out[i] = (i - 1 < Q_ * D_) ? scores[i - 1] : 0.f;
        }
    }
}

// Diagnostic sentinel (mapping failure -> decodable signal, not a crash)
__global__ void diag_kernel(float* out, int missing_mask, int n)
{
    int i = blockIdx.x * blockDim.x + threadIdx.x;
    if (i < n) out[i] = (i == 0) ? (-1.0e6f - (float)missing_mask) : 0.f;
}

// ---------------------------------------------------------------------------
extern "C" void kernel_launch(void* const* d_in, const int* in_sizes, int n_in,
                              void* d_out, int out_size)
{
    const float* qry_hidden = nullptr;   // 786432 elems
    const float* doc_hidden = nullptr;   // 37748736
    const void*  doc_ids    = nullptr;   // 49152
    const float* tok_w      = nullptr;   // 98304
    const float* tok_b      = nullptr;   // 128
    const float* cls_w      = nullptr;   // 589824
    const float* cls_b      = nullptr;   // 768
    const int*   gsize      = nullptr;   // 1
    const void*  cand_a     = nullptr;   // 1024 (ids or mask)
    const void*  cand_b     = nullptr;   // 1024

    long long div = 0;
    for (int i = 0; i < n_in; i++) {
        if (in_sizes[i] == 37748736)  { div = 1; break; }
        if (in_sizes[i] == 150994944) { div = 4; break; }
    }
    if (div == 0) div = 1;

    for (int i = 0; i < n_in; i++) {
        long long sz = (long long)in_sizes[i] / div;
        switch (sz) {
            case 786432:   qry_hidden = (const float*)d_in[i]; break;
            case 37748736: doc_hidden = (const float*)d_in[i]; break;
            case 49152:    doc_ids    = d_in[i];               break;
            case 98304:    tok_w      = (const float*)d_in[i]; break;
            case 128:      tok_b      = (const float*)d_in[i]; break;
            case 589824:   cls_w      = (const float*)d_in[i]; break;
            case 768:      cls_b      = (const float*)d_in[i]; break;
            case 1:        gsize      = (const int*)d_in[i];   break;
            case 1024:
                if (!cand_a) cand_a = d_in[i]; else cand_b = d_in[i];
                break;
            default:
                if (sz == 2 && div == 4) gsize = (const int*)d_in[i];
                break;
        }
    }

    float* out = (float*)d_out;

    int missing = 0;
    if (!qry_hidden) missing |= 1;
    if (!doc_hidden) missing |= 2;
    if (!doc_ids)    missing |= 4;
    if (!tok_w)      missing |= 8;
    if (!tok_b)      missing |= 16;
    if (!cls_w)      missing |= 32;
    if (!cls_b)      missing |= 64;
    if (!cand_a)     missing |= 128;
    if (!cand_b)     missing |= 256;
    if (missing) {
        int n = out_size > 0 ? out_size : 1;
        diag_kernel<<<(n + 255) / 256, 256>>>(out, missing, n);
        return;
    }

    float *doc_reps, *qry_reps, *doc_cls, *qry_cls, *scores;
    cudaGetSymbolAddress((void**)&doc_reps, g_doc_reps);
    cudaGetSymbolAddress((void**)&qry_reps, g_qry_reps);
    cudaGetSymbolAddress((void**)&doc_cls,  g_doc_cls);
    cudaGetSymbolAddress((void**)&qry_cls,  g_qry_cls);
    cudaGetSymbolAddress((void**)&scores,   g_scores);

    // 1) all four projections in ONE double-buffered tensor-core wave
    mega_gemm_tc<<<NB_TOTAL, 256>>>(doc_hidden, qry_hidden,
                                    tok_w, tok_b, cls_w, cls_b,
                                    doc_reps, qry_reps, doc_cls, qry_cls);
    // 2) token scores + fused cls dots -> g_scores
    {
        dim3 grid(Q_, D_ / 8);
        tok_kernel<<<grid, 128>>>(cand_a, cand_b, (const int*)doc_ids, scores);
    }
    // 3) fused loss + output layout
    int mode = (out_size == 1) ? 0 : (out_size == Q_ * D_) ? 1 : 2;
    loss_layout_kernel<<<1, 1024>>>(scores, gsize, out, out_size, mode);
}

// round 13
// speedup vs baseline: 5.8290x; 1.0552x over previous
#include <cuda_runtime.h>

#define Q_  32
#define LQ_ 32
#define D_  256
#define LD_ 192
#define H_  768
#define DT_ 128
#define DC_ 768

// Scratch (allocation-free: __device__ globals)
__device__ float g_doc_reps[(size_t)D_ * LD_ * DT_];   // 25.2 MB
__device__ float g_qry_reps[(size_t)Q_ * LQ_ * DT_];
__device__ float g_doc_cls[(size_t)D_ * DC_];
__device__ float g_qry_cls[(size_t)Q_ * DC_];
__device__ float g_scores[(size_t)Q_ * D_];

// Mega-GEMM block ranges (128x128 output tiles)
#define NB_DOCREP 384
#define NB_QRYREP 8
#define NB_DOCCLS 12
#define NB_QRYCLS 6
#define NB_TOTAL  (NB_DOCREP + NB_QRYREP + NB_DOCCLS + NB_QRYCLS)

#define AS_STRIDE 24      // words per A row: (12*grp+tig)%16 distinct -> conflict-free LDS.64
#define BS_STRIDE 136     // words per B row: (8*tig+grp)%32 distinct -> conflict-free LDS.32

__device__ __forceinline__ unsigned f2tf32(float f) {
    unsigned u;
    asm("cvt.rna.tf32.f32 %0, %1;" : "=r"(u) : "f"(f));
    return u;
}

// ---------------------------------------------------------------------------
// Tensor-core mega-GEMM (tf32 mma.sync.m16n8k8, fp32 accum), double-buffered.
// A staged in (k,k+4)-paired layout for 64-bit conflict-free fragment loads;
// B rows padded to 136 words for conflict-free scalar fragment loads.
// BM=BN=128, BK=16, 256 thr = 8 warps (2x4), warp tile 64x32.
// ---------------------------------------------------------------------------
__global__ __launch_bounds__(256) void mega_gemm_tc(
    const float* __restrict__ doc_hidden,
    const float* __restrict__ qry_hidden,
    const float* __restrict__ tok_w, const float* __restrict__ tok_b,
    const float* __restrict__ cls_w, const float* __restrict__ cls_b,
    float* __restrict__ doc_reps, float* __restrict__ qry_reps,
    float* __restrict__ doc_cls,  float* __restrict__ qry_cls)
{
    const int BK = 16;
    const int NIT = H_ / BK;                     // 48
    __shared__ unsigned As[2][128][AS_STRIDE];   // paired-k layout
    __shared__ unsigned Bs[2][BK][BS_STRIDE];    // [k][n], padded

    // --- segment dispatch ---
    const float* A; const float* B; const float* bias; float* C;
    int lda, ldb, ldc, M, bm, bn, relu;
    int blk = blockIdx.x;
    if (blk < NB_DOCREP) {
        A = doc_hidden; lda = H_;        B = tok_w; ldb = DT_; bias = tok_b;
        C = doc_reps;   ldc = DT_;       M = D_ * LD_;
        bm = blk * 128; bn = 0;          relu = 1;
    } else if (blk < NB_DOCREP + NB_QRYREP) {
        int t = blk - NB_DOCREP;
        A = qry_hidden; lda = H_;        B = tok_w; ldb = DT_; bias = tok_b;
        C = qry_reps;   ldc = DT_;       M = Q_ * LQ_;
        bm = t * 128;   bn = 0;          relu = 1;
    } else if (blk < NB_DOCREP + NB_QRYREP + NB_DOCCLS) {
        int t = blk - NB_DOCREP - NB_QRYREP;
        A = doc_hidden; lda = LD_ * H_;  B = cls_w; ldb = DC_; bias = cls_b;
        C = doc_cls;    ldc = DC_;       M = D_;
        bm = (t % 2) * 128; bn = (t / 2) * 128; relu = 0;
    } else {
        int t = blk - NB_DOCREP - NB_QRYREP - NB_DOCCLS;
        A = qry_hidden; lda = LQ_ * H_;  B = cls_w; ldb = DC_; bias = cls_b;
        C = qry_cls;    ldc = DC_;       M = Q_;
        bm = 0;         bn = t * 128;    relu = 0;
    }

    int tid  = threadIdx.x;
    int lane = tid & 31;
    int wid  = tid >> 5;
    int warp_m = (wid >> 2) * 64;
    int warp_n = (wid & 3) * 32;
    int grp = lane >> 2;
    int tig = lane & 3;

    float c[4][4][4];
#pragma unroll
    for (int mt = 0; mt < 4; mt++)
#pragma unroll
        for (int nt = 0; nt < 4; nt++)
#pragma unroll
            for (int r = 0; r < 4; r++) c[mt][nt][r] = 0.f;

    int a_row = tid >> 1;             // 0..127
    int a_col = (tid & 1) * 8;        // ks-group base: 0 | 8
    int b_row = tid >> 4;             // 0..15
    int b_col = (tid & 15) * 8;       // 0..120
    bool a_ok = (bm + a_row < M);
    const float* a_src = A + (size_t)(bm + a_row) * lda + a_col;
    const float* b_src = B + (size_t)b_row * ldb + bn + b_col;

    float va[8], vb[8];
    // staging store helper: paired-k permutation
    //   slots a_col+0..3 = {v0, v4, v1, v5}; a_col+4..7 = {v2, v6, v3, v7}
#define STAGE_A(buf) do {                                                     \
        *reinterpret_cast<uint4*>(&As[buf][a_row][a_col]) =                   \
            make_uint4(f2tf32(va[0]), f2tf32(va[4]), f2tf32(va[1]), f2tf32(va[5])); \
        *reinterpret_cast<uint4*>(&As[buf][a_row][a_col + 4]) =               \
            make_uint4(f2tf32(va[2]), f2tf32(va[6]), f2tf32(va[3]), f2tf32(va[7])); \
    } while (0)
#define STAGE_B(buf) do {                                                     \
        *reinterpret_cast<uint4*>(&Bs[buf][b_row][b_col]) =                   \
            make_uint4(f2tf32(vb[0]), f2tf32(vb[1]), f2tf32(vb[2]), f2tf32(vb[3])); \
        *reinterpret_cast<uint4*>(&Bs[buf][b_row][b_col + 4]) =               \
            make_uint4(f2tf32(vb[4]), f2tf32(vb[5]), f2tf32(vb[6]), f2tf32(vb[7])); \
    } while (0)

    // --- prologue: load slab 0 ---
    if (a_ok) {
        float4 t0 = *reinterpret_cast<const float4*>(a_src);
        float4 t1 = *reinterpret_cast<const float4*>(a_src + 4);
        va[0]=t0.x; va[1]=t0.y; va[2]=t0.z; va[3]=t0.w;
        va[4]=t1.x; va[5]=t1.y; va[6]=t1.z; va[7]=t1.w;
    } else {
#pragma unroll
        for (int j = 0; j < 8; j++) va[j] = 0.f;
    }
    {
        float4 t0 = *reinterpret_cast<const float4*>(b_src);
        float4 t1 = *reinterpret_cast<const float4*>(b_src + 4);
        vb[0]=t0.x; vb[1]=t0.y; vb[2]=t0.z; vb[3]=t0.w;
        vb[4]=t1.x; vb[5]=t1.y; vb[6]=t1.z; vb[7]=t1.w;
    }
    STAGE_A(0);
    STAGE_B(0);
    __syncthreads();

    for (int it = 0; it < NIT; it++) {
        int cur = it & 1;
        // --- issue next-slab global loads early (latency overlap) ---
        if (it + 1 < NIT) {
            int k0 = (it + 1) * BK;
            if (a_ok) {
                float4 t0 = *reinterpret_cast<const float4*>(a_src + k0);
                float4 t1 = *reinterpret_cast<const float4*>(a_src + k0 + 4);
                va[0]=t0.x; va[1]=t0.y; va[2]=t0.z; va[3]=t0.w;
                va[4]=t1.x; va[5]=t1.y; va[6]=t1.z; va[7]=t1.w;
            }
            float4 t0 = *reinterpret_cast<const float4*>(b_src + (size_t)k0 * ldb);
            float4 t1 = *reinterpret_cast<const float4*>(b_src + (size_t)k0 * ldb + 4);
            vb[0]=t0.x; vb[1]=t0.y; vb[2]=t0.z; vb[3]=t0.w;
            vb[4]=t1.x; vb[5]=t1.y; vb[6]=t1.z; vb[7]=t1.w;
        }

        // --- MMA on current buffer ---
#pragma unroll
        for (int ks = 0; ks < 2; ks++) {
            int kb = ks * 8;                 // slot-group base AND k base
            unsigned bf[4][2];
#pragma unroll
            for (int nt = 0; nt < 4; nt++) {
                int n = warp_n + nt * 8 + grp;
                bf[nt][0] = Bs[cur][kb + tig][n];
                bf[nt][1] = Bs[cur][kb + tig + 4][n];
            }
#pragma unroll
            for (int mt = 0; mt < 4; mt++) {
                int m = warp_m + mt * 16 + grp;
                // paired layout: (a0,a2) adjacent at slot kb + tig*2, (a1,a3) at m+8
                uint2 p02 = *reinterpret_cast<const uint2*>(&As[cur][m][kb + tig * 2]);
                uint2 p13 = *reinterpret_cast<const uint2*>(&As[cur][m + 8][kb + tig * 2]);
#pragma unroll
                for (int nt = 0; nt < 4; nt++) {
                    asm volatile(
                        "mma.sync.aligned.m16n8k8.row.col.f32.tf32.tf32.f32 "
                        "{%0,%1,%2,%3}, {%4,%5,%6,%7}, {%8,%9}, {%0,%1,%2,%3};\n"
                        : "+f"(c[mt][nt][0]), "+f"(c[mt][nt][1]),
                          "+f"(c[mt][nt][2]), "+f"(c[mt][nt][3])
                        : "r"(p02.x), "r"(p13.x), "r"(p02.y), "r"(p13.y),
                          "r"(bf[nt][0]), "r"(bf[nt][1]));
                }
            }
        }

        // --- convert & stage next slab into the other buffer ---
        if (it + 1 < NIT) {
            int nxt = 1 - cur;
            STAGE_A(nxt);
            STAGE_B(nxt);
        }
        __syncthreads();
    }

    // --- epilogue: bias (+relu), float2 stores ---
#pragma unroll
    for (int mt = 0; mt < 4; mt++) {
#pragma unroll
        for (int nt = 0; nt < 4; nt++) {
            int m0 = bm + warp_m + mt * 16 + grp;
            int n0 = bn + warp_n + nt * 8 + tig * 2;
            float b0 = bias[n0], b1 = bias[n0 + 1];
            if (m0 < M) {
                float v0 = c[mt][nt][0] + b0;
                float v1 = c[mt][nt][1] + b1;
                if (relu) { v0 = fmaxf(v0, 0.f); v1 = fmaxf(v1, 0.f); }
                *reinterpret_cast<float2*>(C + (size_t)m0 * ldc + n0) = make_float2(v0, v1);
            }
            if (m0 + 8 < M) {
                float v2 = c[mt][nt][2] + b0;
                float v3 = c[mt][nt][3] + b1;
                if (relu) { v2 = fmaxf(v2, 0.f); v3 = fmaxf(v3, 0.f); }
                *reinterpret_cast<float2*>(C + (size_t)(m0 + 8) * ldc + n0) = make_float2(v2, v3);
            }
        }
    }
#undef STAGE_A
#undef STAGE_B
}

// Disambiguate the two 1024-element inputs on device.
__device__ __forceinline__ bool is_mask_arr(const void* p) {
    const unsigned* u = (const unsigned*)p;
    return u[0] == 0x3F800000u && u[1] == 0x3F800000u && u[2] == 0x3F800000u;
}

// ---------------------------------------------------------------------------
// Sparse exact-match token scoring + fused cls dot. Block = (q, 8 docs).
// ---------------------------------------------------------------------------
__global__ __launch_bounds__(128) void tok_kernel(
    const void* __restrict__ cand_a, const void* __restrict__ cand_b,
    const int* __restrict__ dids_g,
    float* __restrict__ scores)
{
    bool a_mask = is_mask_arr(cand_a);
    const int*   qids_g  = (const int*)  (a_mask ? cand_b : cand_a);
    const float* qmask_g = (const float*)(a_mask ? cand_a : cand_b);

    __shared__ float qs[LQ_][DT_];     // 16 KB
    __shared__ float qcls[DC_];        // 3 KB
    __shared__ int   s_qids[LQ_];
    __shared__ float s_qmask[LQ_];
    __shared__ int   s_dids[LD_];
    __shared__ float warp_acc[4];
    __shared__ float warp_cls[4];

    int q   = blockIdx.x;
    int d0  = blockIdx.y * 8;
    int tid = threadIdx.x;
    int lane = tid & 31;
    int w    = tid >> 5;

    for (int t = tid; t < LQ_ * DT_; t += 128)
        qs[t / DT_][t % DT_] = g_qry_reps[(size_t)q * LQ_ * DT_ + t];
    for (int t = tid; t < DC_; t += 128)
        qcls[t] = g_qry_cls[(size_t)q * DC_ + t];
    if (tid < LQ_) {
        s_qids[tid]  = qids_g[q * LQ_ + tid];
        s_qmask[tid] = qmask_g[q * LQ_ + tid];
    }
    __syncthreads();

    for (int dd = 0; dd < 8; dd++) {
        int d = d0 + dd;
        for (int t = tid; t < LD_; t += 128)
            s_dids[t] = dids_g[d * LD_ + t];
        __syncthreads();

        const float* drep = g_doc_reps + (size_t)d * LD_ * DT_;
        float acc = 0.f;

        for (int i = 1 + w; i < LQ_; i += 4) {
            int tok = s_qids[i];
            float best = 0.f;
#pragma unroll
            for (int jb = 0; jb < LD_; jb += 32) {
                int j = jb + lane;
                unsigned mask = __ballot_sync(0xffffffffu, s_dids[j] == tok);
                while (mask) {
                    int jj = jb + (__ffs(mask) - 1);
                    mask &= mask - 1;
                    const float* dr = drep + (size_t)jj * DT_;
                    float p = qs[i][lane]      * dr[lane]
                            + qs[i][lane + 32] * dr[lane + 32]
                            + qs[i][lane + 64] * dr[lane + 64]
                            + qs[i][lane + 96] * dr[lane + 96];
#pragma unroll
                    for (int off = 16; off > 0; off >>= 1)
                        p += __shfl_xor_sync(0xffffffffu, p, off);
                    best = fmaxf(best, p);
                }
            }
            acc += best * s_qmask[i];
        }

        const float* dcls = g_doc_cls + (size_t)d * DC_;
        float pc = 0.f;
#pragma unroll
        for (int k = 0; k < DC_ / 128; k++)
            pc += qcls[k * 128 + tid] * dcls[k * 128 + tid];
#pragma unroll
        for (int off = 16; off > 0; off >>= 1)
            pc += __shfl_xor_sync(0xffffffffu, pc, off);

        if (lane == 0) { warp_acc[w] = acc; warp_cls[w] = pc; }
        __syncthreads();
        if (tid == 0)
            scores[q * D_ + d] = warp_acc[0] + warp_acc[1] + warp_acc[2] + warp_acc[3]
                               + warp_cls[0] + warp_cls[1] + warp_cls[2] + warp_cls[3];
        __syncthreads();
    }
}

// ---------------------------------------------------------------------------
// Fused loss + output layout.
// ---------------------------------------------------------------------------
__global__ __launch_bounds__(1024) void loss_layout_kernel(
    const float* __restrict__ scores, const int* __restrict__ gs,
    float* __restrict__ out, int out_size, int mode)
{
    __shared__ float wloss[32];
    __shared__ float s_loss;
    int tid = threadIdx.x;
    int lane = tid & 31;
    int w = tid >> 5;

    const float* row = scores + (size_t)w * D_;
    float m = -1e30f;
    for (int c = lane; c < D_; c += 32) m = fmaxf(m, row[c]);
#pragma unroll
    for (int off = 16; off > 0; off >>= 1)
        m = fmaxf(m, __shfl_xor_sync(0xffffffffu, m, off));
    float s = 0.f;
    for (int c = lane; c < D_; c += 32) s += expf(row[c] - m);
#pragma unroll
    for (int off = 16; off > 0; off >>= 1)
        s += __shfl_xor_sync(0xffffffffu, s, off);

    int group = 8;
    if (gs) {
        int gv = gs[0];
        if (gv >= 1 && gv * 31 < D_) group = gv;
    }
    int label = w * group;
    float logp = row[label] - m - logf(s);
    if (lane == 0) wloss[w] = -logp;
    __syncthreads();
    if (tid == 0) {
        float t = 0.f;
        for (int i = 0; i < 32; i++) t += wloss[i];
        s_loss = t / 32.f;
    }
    __syncthreads();

    float loss = s_loss;
    for (int i = tid; i < out_size; i += 1024) {
        if (mode == 0) {
            if (i == 0) out[0] = loss;
        } else if (mode == 1) {
            out[i] = (i < Q_ * D_) ? scores[i] : 0.f;
        } else {
            if (i == 0) out[0] = loss;
            else out[i] = (i - 1 < Q_ * D_) ? scores[i - 1] : 0.f;
        }
    }
}

// Diagnostic sentinel
__global__ void diag_kernel(float* out, int missing_mask, int n)
{
    int i = blockIdx.x * blockDim.x + threadIdx.x;
    if (i < n) out[i] = (i == 0) ? (-1.0e6f - (float)missing_mask) : 0.f;
}

// ---------------------------------------------------------------------------
extern "C" void kernel_launch(void* const* d_in, const int* in_sizes, int n_in,
                              void* d_out, int out_size)
{
    const float* qry_hidden = nullptr;
    const float* doc_hidden = nullptr;
    const void*  doc_ids    = nullptr;
    const float* tok_w      = nullptr;
    const float* tok_b      = nullptr;
    const float* cls_w      = nullptr;
    const float* cls_b      = nullptr;
    const int*   gsize      = nullptr;
    const void*  cand_a     = nullptr;
    const void*  cand_b     = nullptr;

    long long div = 0;
    for (int i = 0; i < n_in; i++) {
        if (in_sizes[i] == 37748736)  { div = 1; break; }
        if (in_sizes[i] == 150994944) { div = 4; break; }
    }
    if (div == 0) div = 1;

    for (int i = 0; i < n_in; i++) {
        long long sz = (long long)in_sizes[i] / div;
        switch (sz) {
            case 786432:   qry_hidden = (const float*)d_in[i]; break;
            case 37748736: doc_hidden = (const float*)d_in[i]; break;
            case 49152:    doc_ids    = d_in[i];               break;
            case 98304:    tok_w      = (const float*)d_in[i]; break;
            case 128:      tok_b      = (const float*)d_in[i]; break;
            case 589824:   cls_w      = (const float*)d_in[i]; break;
            case 768:      cls_b      = (const float*)d_in[i]; break;
            case 1:        gsize      = (const int*)d_in[i];   break;
            case 1024:
                if (!cand_a) cand_a = d_in[i]; else cand_b = d_in[i];
                break;
            default:
                if (sz == 2 && div == 4) gsize = (const int*)d_in[i];
                break;
        }
    }

    float* out = (float*)d_out;

    int missing = 0;
    if (!qry_hidden) missing |= 1;
    if (!doc_hidden) missing |= 2;
    if (!doc_ids)    missing |= 4;
    if (!tok_w)      missing |= 8;
    if (!tok_b)      missing |= 16;
    if (!cls_w)      missing |= 32;
    if (!cls_b)      missing |= 64;
    if (!cand_a)     missing |= 128;
    if (!cand_b)     missing |= 256;
    if (missing) {
        int n = out_size > 0 ? out_size : 1;
        diag_kernel<<<(n + 255) / 256, 256>>>(out, missing, n);
        return;
    }

    float *doc_reps, *qry_reps, *doc_cls, *qry_cls, *scores;
    cudaGetSymbolAddress((void**)&doc_reps, g_doc_reps);
    cudaGetSymbolAddress((void**)&qry_reps, g_qry_reps);
    cudaGetSymbolAddress((void**)&doc_cls,  g_doc_cls);
    cudaGetSymbolAddress((void**)&qry_cls,  g_qry_cls);
    cudaGetSymbolAddress((void**)&scores,   g_scores);

    mega_gemm_tc<<<NB_TOTAL, 256>>>(doc_hidden, qry_hidden,
                                    tok_w, tok_b, cls_w, cls_b,
                                    doc_reps, qry_reps, doc_cls, qry_cls);
    {
        dim3 grid(Q_, D_ / 8);
        tok_kernel<<<grid, 128>>>(cand_a, cand_b, (const int*)doc_ids, scores);
    }
    int mode = (out_size == 1) ? 0 : (out_size == Q_ * D_) ? 1 : 2;
    loss_layout_kernel<<<1, 1024>>>(scores, gsize, out, out_size, mode);
}

// round 14
// speedup vs baseline: 6.6490x; 1.1407x over previous
#include <cuda_runtime.h>
#include <cuda_fp16.h>

#define Q_  32
#define LQ_ 32
#define D_  256
#define LD_ 192
#define H_  768
#define DT_ 128
#define DC_ 768

// Scratch (allocation-free: __device__ globals)
__device__ float g_doc_reps[(size_t)D_ * LD_ * DT_];   // 25.2 MB
__device__ float g_qry_reps[(size_t)Q_ * LQ_ * DT_];
__device__ float g_doc_cls[(size_t)D_ * DC_];
__device__ float g_qry_cls[(size_t)Q_ * DC_];
__device__ float g_scores[(size_t)Q_ * D_];

// Mega-GEMM block ranges (128x128 output tiles)
#define NB_DOCREP 384
#define NB_QRYREP 8
#define NB_DOCCLS 12
#define NB_QRYCLS 6
#define NB_TOTAL  (NB_DOCREP + NB_QRYREP + NB_DOCCLS + NB_QRYCLS)

#define AS_STRIDE 8       // uints (half2) per A row; frag LDS.64 conflict-free
#define BS_STRIDE 136     // uints per B k-pair row; 136%32==8 -> (8*tig+grp) distinct

__device__ __forceinline__ unsigned pack_h2(float lo, float hi) {
    __half2 h = __floats2half2_rn(lo, hi);   // .x = lo half (lower k index)
    return *reinterpret_cast<unsigned*>(&h);
}

// ---------------------------------------------------------------------------
// fp16 tensor-core mega-GEMM (mma.m16n8k16.row.col.f32.f16.f16.f32),
// double-buffered. A staged as interleaved (k-lo,k-hi) half2 pairs so each
// thread's 4 A-fragment regs come from 2x LDS.64; B staged as k-paired half2
// rows so b0/b1 are 2x conflict-free LDS.32.
// BM=BN=128, BK=16, 256 thr = 8 warps (2x4), warp tile 64x32.
// ---------------------------------------------------------------------------
__global__ __launch_bounds__(256) void mega_gemm_tc(
    const float* __restrict__ doc_hidden,
    const float* __restrict__ qry_hidden,
    const float* __restrict__ tok_w, const float* __restrict__ tok_b,
    const float* __restrict__ cls_w, const float* __restrict__ cls_b,
    float* __restrict__ doc_reps, float* __restrict__ qry_reps,
    float* __restrict__ doc_cls,  float* __restrict__ qry_cls)
{
    const int BK = 16;
    const int NIT = H_ / BK;                     // 48
    __shared__ unsigned As[2][128 * AS_STRIDE];  // [buf][m*8 + slot]
    __shared__ unsigned Bs[2][8 * BS_STRIDE];    // [buf][k2*136 + n]

    // --- segment dispatch ---
    const float* A; const float* B; const float* bias; float* C;
    int lda, ldb, ldc, M, bm, bn, relu;
    int blk = blockIdx.x;
    if (blk < NB_DOCREP) {
        A = doc_hidden; lda = H_;        B = tok_w; ldb = DT_; bias = tok_b;
        C = doc_reps;   ldc = DT_;       M = D_ * LD_;
        bm = blk * 128; bn = 0;          relu = 1;
    } else if (blk < NB_DOCREP + NB_QRYREP) {
        int t = blk - NB_DOCREP;
        A = qry_hidden; lda = H_;        B = tok_w; ldb = DT_; bias = tok_b;
        C = qry_reps;   ldc = DT_;       M = Q_ * LQ_;
        bm = t * 128;   bn = 0;          relu = 1;
    } else if (blk < NB_DOCREP + NB_QRYREP + NB_DOCCLS) {
        int t = blk - NB_DOCREP - NB_QRYREP;
        A = doc_hidden; lda = LD_ * H_;  B = cls_w; ldb = DC_; bias = cls_b;
        C = doc_cls;    ldc = DC_;       M = D_;
        bm = (t % 2) * 128; bn = (t / 2) * 128; relu = 0;
    } else {
        int t = blk - NB_DOCREP - NB_QRYREP - NB_DOCCLS;
        A = qry_hidden; lda = LQ_ * H_;  B = cls_w; ldb = DC_; bias = cls_b;
        C = qry_cls;    ldc = DC_;       M = Q_;
        bm = 0;         bn = t * 128;    relu = 0;
    }

    int tid  = threadIdx.x;
    int lane = tid & 31;
    int wid  = tid >> 5;
    int warp_m = (wid >> 2) * 64;
    int warp_n = (wid & 3) * 32;
    int grp = lane >> 2;
    int tig = lane & 3;

    float c[4][4][4];
#pragma unroll
    for (int mt = 0; mt < 4; mt++)
#pragma unroll
        for (int nt = 0; nt < 4; nt++)
#pragma unroll
            for (int r = 0; r < 4; r++) c[mt][nt][r] = 0.f;

    // A staging: thread -> (row, sel). Loads float4 at k = sel*4 and sel*4+8;
    // packs 4 half2 slots at slot base row*8 + sel*4:
    //   sel=0: slots {(k0,k1),(k8,k9),(k2,k3),(k10,k11)}
    //   sel=1: slots {(k4,k5),(k12,k13),(k6,k7),(k14,k15)}
    // Fragment read: uint2 at row*8 + 2*tig = ((k2t,k2t+1),(k2t+8,k2t+9)).
    int a_row = tid >> 1;
    int a_sel = tid & 1;
    bool a_ok = (bm + a_row < M);
    const float* a_src = A + (size_t)(bm + a_row) * lda + a_sel * 4;

    // B staging: thread -> (k2 = tid>>5 in 0..7, n_base = (tid&31)*4).
    // Loads float4 from global rows 2*k2 and 2*k2+1; packs half2(k-even,k-odd).
    int b_k2 = tid >> 5;
    int b_nb = (tid & 31) * 4;
    const float* b_src0 = B + (size_t)(2 * b_k2)     * ldb + bn + b_nb;
    const float* b_src1 = B + (size_t)(2 * b_k2 + 1) * ldb + bn + b_nb;

    float va0[4], va1[4], vb0[4], vb1[4];

#define LOAD_SLAB(k0) do {                                                    \
        if (a_ok) {                                                           \
            float4 t0 = *reinterpret_cast<const float4*>(a_src + (k0));       \
            float4 t1 = *reinterpret_cast<const float4*>(a_src + (k0) + 8);   \
            va0[0]=t0.x; va0[1]=t0.y; va0[2]=t0.z; va0[3]=t0.w;               \
            va1[0]=t1.x; va1[1]=t1.y; va1[2]=t1.z; va1[3]=t1.w;               \
        } else {                                                              \
            va0[0]=va0[1]=va0[2]=va0[3]=0.f;                                  \
            va1[0]=va1[1]=va1[2]=va1[3]=0.f;                                  \
        }                                                                     \
        float4 u0 = *reinterpret_cast<const float4*>(b_src0 + (size_t)(k0) * ldb); \
        float4 u1 = *reinterpret_cast<const float4*>(b_src1 + (size_t)(k0) * ldb); \
        vb0[0]=u0.x; vb0[1]=u0.y; vb0[2]=u0.z; vb0[3]=u0.w;                   \
        vb1[0]=u1.x; vb1[1]=u1.y; vb1[2]=u1.z; vb1[3]=u1.w;                   \
    } while (0)

#define STAGE(buf) do {                                                      \
        *reinterpret_cast<uint4*>(&As[buf][a_row * AS_STRIDE + a_sel * 4]) =  \
            make_uint4(pack_h2(va0[0], va0[1]), pack_h2(va1[0], va1[1]),      \
                       pack_h2(va0[2], va0[3]), pack_h2(va1[2], va1[3]));     \
        *reinterpret_cast<uint4*>(&Bs[buf][b_k2 * BS_STRIDE + b_nb]) =        \
            make_uint4(pack_h2(vb0[0], vb1[0]), pack_h2(vb0[1], vb1[1]),      \
                       pack_h2(vb0[2], vb1[2]), pack_h2(vb0[3], vb1[3]));     \
    } while (0)

    // --- prologue ---
    LOAD_SLAB(0);
    STAGE(0);
    __syncthreads();

    for (int it = 0; it < NIT; it++) {
        int cur = it & 1;
        if (it + 1 < NIT) LOAD_SLAB((it + 1) * BK);

        // --- MMA on current buffer: 16x mma.m16n8k16 ---
        unsigned bf[4][2];
#pragma unroll
        for (int nt = 0; nt < 4; nt++) {
            int n = warp_n + nt * 8 + grp;
            bf[nt][0] = Bs[cur][tig * BS_STRIDE + n];
            bf[nt][1] = Bs[cur][(tig + 4) * BS_STRIDE + n];
        }
#pragma unroll
        for (int mt = 0; mt < 4; mt++) {
            int m = warp_m + mt * 16 + grp;
            uint2 plo = *reinterpret_cast<const uint2*>(&As[cur][m * AS_STRIDE + tig * 2]);
            uint2 phi = *reinterpret_cast<const uint2*>(&As[cur][(m + 8) * AS_STRIDE + tig * 2]);
#pragma unroll
            for (int nt = 0; nt < 4; nt++) {
                asm volatile(
                    "mma.sync.aligned.m16n8k16.row.col.f32.f16.f16.f32 "
                    "{%0,%1,%2,%3}, {%4,%5,%6,%7}, {%8,%9}, {%0,%1,%2,%3};\n"
                    : "+f"(c[mt][nt][0]), "+f"(c[mt][nt][1]),
                      "+f"(c[mt][nt][2]), "+f"(c[mt][nt][3])
                    : "r"(plo.x), "r"(phi.x), "r"(plo.y), "r"(phi.y),
                      "r"(bf[nt][0]), "r"(bf[nt][1]));
            }
        }

        if (it + 1 < NIT) STAGE(1 - cur);
        __syncthreads();
    }
#undef LOAD_SLAB
#undef STAGE

    // --- epilogue: bias (+relu), float2 stores ---
#pragma unroll
    for (int mt = 0; mt < 4; mt++) {
#pragma unroll
        for (int nt = 0; nt < 4; nt++) {
            int m0 = bm + warp_m + mt * 16 + grp;
            int n0 = bn + warp_n + nt * 8 + tig * 2;
            float b0 = bias[n0], b1 = bias[n0 + 1];
            if (m0 < M) {
                float v0 = c[mt][nt][0] + b0;
                float v1 = c[mt][nt][1] + b1;
                if (relu) { v0 = fmaxf(v0, 0.f); v1 = fmaxf(v1, 0.f); }
                *reinterpret_cast<float2*>(C + (size_t)m0 * ldc + n0) = make_float2(v0, v1);
            }
            if (m0 + 8 < M) {
                float v2 = c[mt][nt][2] + b0;
                float v3 = c[mt][nt][3] + b1;
                if (relu) { v2 = fmaxf(v2, 0.f); v3 = fmaxf(v3, 0.f); }
                *reinterpret_cast<float2*>(C + (size_t)(m0 + 8) * ldc + n0) = make_float2(v2, v3);
            }
        }
    }
}

// Disambiguate the two 1024-element inputs on device.
__device__ __forceinline__ bool is_mask_arr(const void* p) {
    const unsigned* u = (const unsigned*)p;
    return u[0] == 0x3F800000u && u[1] == 0x3F800000u && u[2] == 0x3F800000u;
}

// ---------------------------------------------------------------------------
// Sparse exact-match token scoring + fused cls dot. Block = (q, 8 docs).
// ---------------------------------------------------------------------------
__global__ __launch_bounds__(128) void tok_kernel(
    const void* __restrict__ cand_a, const void* __restrict__ cand_b,
    const int* __restrict__ dids_g,
    float* __restrict__ scores)
{
    bool a_mask = is_mask_arr(cand_a);
    const int*   qids_g  = (const int*)  (a_mask ? cand_b : cand_a);
    const float* qmask_g = (const float*)(a_mask ? cand_a : cand_b);

    __shared__ float qs[LQ_][DT_];     // 16 KB
    __shared__ float qcls[DC_];        // 3 KB
    __shared__ int   s_qids[LQ_];
    __shared__ float s_qmask[LQ_];
    __shared__ int   s_dids[LD_];
    __shared__ float warp_acc[4];
    __shared__ float warp_cls[4];

    int q   = blockIdx.x;
    int d0  = blockIdx.y * 8;
    int tid = threadIdx.x;
    int lane = tid & 31;
    int w    = tid >> 5;

    for (int t = tid; t < LQ_ * DT_; t += 128)
        qs[t / DT_][t % DT_] = g_qry_reps[(size_t)q * LQ_ * DT_ + t];
    for (int t = tid; t < DC_; t += 128)
        qcls[t] = g_qry_cls[(size_t)q * DC_ + t];
    if (tid < LQ_) {
        s_qids[tid]  = qids_g[q * LQ_ + tid];
        s_qmask[tid] = qmask_g[q * LQ_ + tid];
    }
    __syncthreads();

    for (int dd = 0; dd < 8; dd++) {
        int d = d0 + dd;
        for (int t = tid; t < LD_; t += 128)
            s_dids[t] = dids_g[d * LD_ + t];
        __syncthreads();

        const float* drep = g_doc_reps + (size_t)d * LD_ * DT_;
        float acc = 0.f;

        for (int i = 1 + w; i < LQ_; i += 4) {
            int tok = s_qids[i];
            float best = 0.f;
#pragma unroll
            for (int jb = 0; jb < LD_; jb += 32) {
                int j = jb + lane;
                unsigned mask = __ballot_sync(0xffffffffu, s_dids[j] == tok);
                while (mask) {
                    int jj = jb + (__ffs(mask) - 1);
                    mask &= mask - 1;
                    const float* dr = drep + (size_t)jj * DT_;
                    float p = qs[i][lane]      * dr[lane]
                            + qs[i][lane + 32] * dr[lane + 32]
                            + qs[i][lane + 64] * dr[lane + 64]
                            + qs[i][lane + 96] * dr[lane + 96];
#pragma unroll
                    for (int off = 16; off > 0; off >>= 1)
                        p += __shfl_xor_sync(0xffffffffu, p, off);
                    best = fmaxf(best, p);
                }
            }
            acc += best * s_qmask[i];
        }

        const float* dcls = g_doc_cls + (size_t)d * DC_;
        float pc = 0.f;
#pragma unroll
        for (int k = 0; k < DC_ / 128; k++)
            pc += qcls[k * 128 + tid] * dcls[k * 128 + tid];
#pragma unroll
        for (int off = 16; off > 0; off >>= 1)
            pc += __shfl_xor_sync(0xffffffffu, pc, off);

        if (lane == 0) { warp_acc[w] = acc; warp_cls[w] = pc; }
        __syncthreads();
        if (tid == 0)
            scores[q * D_ + d] = warp_acc[0] + warp_acc[1] + warp_acc[2] + warp_acc[3]
                               + warp_cls[0] + warp_cls[1] + warp_cls[2] + warp_cls[3];
        __syncthreads();
    }
}

// ---------------------------------------------------------------------------
// Fused loss + output layout.
// ---------------------------------------------------------------------------
__global__ __launch_bounds__(1024) void loss_layout_kernel(
    const float* __restrict__ scores, const int* __restrict__ gs,
    float* __restrict__ out, int out_size, int mode)
{
    __shared__ float wloss[32];
    __shared__ float s_loss;
    int tid = threadIdx.x;
    int lane = tid & 31;
    int w = tid >> 5;

    const float* row = scores + (size_t)w * D_;
    float m = -1e30f;
    for (int c = lane; c < D_; c += 32) m = fmaxf(m, row[c]);
#pragma unroll
    for (int off = 16; off > 0; off >>= 1)
        m = fmaxf(m, __shfl_xor_sync(0xffffffffu, m, off));
    float s = 0.f;
    for (int c = lane; c < D_; c += 32) s += expf(row[c] - m);
#pragma unroll
    for (int off = 16; off > 0; off >>= 1)
        s += __shfl_xor_sync(0xffffffffu, s, off);

    int group = 8;
    if (gs) {
        int gv = gs[0];
        if (gv >= 1 && gv * 31 < D_) group = gv;
    }
    int label = w * group;
    float logp = row[label] - m - logf(s);
    if (lane == 0) wloss[w] = -logp;
    __syncthreads();
    if (tid == 0) {
        float t = 0.f;
        for (int i = 0; i < 32; i++) t += wloss[i];
        s_loss = t / 32.f;
    }
    __syncthreads();

    float loss = s_loss;
    for (int i = tid; i < out_size; i += 1024) {
        if (mode == 0) {
            if (i == 0) out[0] = loss;
        } else if (mode == 1) {
            out[i] = (i < Q_ * D_) ? scores[i] : 0.f;
        } else {
            if (i == 0) out[0] = loss;
            else out[i] = (i - 1 < Q_ * D_) ? scores[i - 1] : 0.f;
        }
    }
}

// Diagnostic sentinel
__global__ void diag_kernel(float* out, int missing_mask, int n)
{
    int i = blockIdx.x * blockDim.x + threadIdx.x;
    if (i < n) out[i] = (i == 0) ? (-1.0e6f - (float)missing_mask) : 0.f;
}

// ---------------------------------------------------------------------------
extern "C" void kernel_launch(void* const* d_in, const int* in_sizes, int n_in,
                              void* d_out, int out_size)
{
    const float* qry_hidden = nullptr;
    const float* doc_hidden = nullptr;
    const void*  doc_ids    = nullptr;
    const float* tok_w      = nullptr;
    const float* tok_b      = nullptr;
    const float* cls_w      = nullptr;
    const float* cls_b      = nullptr;
    const int*   gsize      = nullptr;
    const void*  cand_a     = nullptr;
    const void*  cand_b     = nullptr;

    long long div = 0;
    for (int i = 0; i < n_in; i++) {
        if (in_sizes[i] == 37748736)  { div = 1; break; }
        if (in_sizes[i] == 150994944) { div = 4; break; }
    }
    if (div == 0) div = 1;

    for (int i = 0; i < n_in; i++) {
        long long sz = (long long)in_sizes[i] / div;
        switch (sz) {
            case 786432:   qry_hidden = (const float*)d_in[i]; break;
            case 37748736: doc_hidden = (const float*)d_in[i]; break;
            case 49152:    doc_ids    = d_in[i];               break;
            case 98304:    tok_w      = (const float*)d_in[i]; break;
            case 128:      tok_b      = (const float*)d_in[i]; break;
            case 589824:   cls_w      = (const float*)d_in[i]; break;
            case 768:      cls_b      = (const float*)d_in[i]; break;
            case 1:        gsize      = (const int*)d_in[i];   break;
            case 1024:
                if (!cand_a) cand_a = d_in[i]; else cand_b = d_in[i];
                break;
            default:
                if (sz == 2 && div == 4) gsize = (const int*)d_in[i];
                break;
        }
    }

    float* out = (float*)d_out;

    int missing = 0;
    if (!qry_hidden) missing |= 1;
    if (!doc_hidden) missing |= 2;
    if (!doc_ids)    missing |= 4;
    if (!tok_w)      missing |= 8;
    if (!tok_b)      missing |= 16;
    if (!cls_w)      missing |= 32;
    if (!cls_b)      missing |= 64;
    if (!cand_a)     missing |= 128;
    if (!cand_b)     missing |= 256;
    if (missing) {
        int n = out_size > 0 ? out_size : 1;
        diag_kernel<<<(n + 255) / 256, 256>>>(out, missing, n);
        return;
    }

    float *doc_reps, *qry_reps, *doc_cls, *qry_cls, *scores;
    cudaGetSymbolAddress((void**)&doc_reps, g_doc_reps);
    cudaGetSymbolAddress((void**)&qry_reps, g_qry_reps);
    cudaGetSymbolAddress((void**)&doc_cls,  g_doc_cls);
    cudaGetSymbolAddress((void**)&qry_cls,  g_qry_cls);
    cudaGetSymbolAddress((void**)&scores,   g_scores);

    mega_gemm_tc<<<NB_TOTAL, 256>>>(doc_hidden, qry_hidden,
                                    tok_w, tok_b, cls_w, cls_b,
                                    doc_reps, qry_reps, doc_cls, qry_cls);
    {
        dim3 grid(Q_, D_ / 8);
        tok_kernel<<<grid, 128>>>(cand_a, cand_b, (const int*)doc_ids, scores);
    }
    int mode = (out_size == 1) ? 0 : (out_size == Q_ * D_) ? 1 : 2;
    loss_layout_kernel<<<1, 1024>>>(scores, gsize, out, out_size, mode);
}